// round 6
// baseline (speedup 1.0000x reference)
#include <cuda_runtime.h>
#include <cuda_bf16.h>
#include <math.h>
#include <stdint.h>

// Problem constants (fixed by the reference setup)
#define BB   8
#define TT   1024
#define TEE  1024
#define HH   1024
#define NHH  8
#define DKK  128
#define MM   (BB * TT)       // 8192 rows for projections
#define FF   4096            // FFN hidden

// ---------------------------------------------------------------------------
// Scratch (static device globals)
// ---------------------------------------------------------------------------
__device__ float ws_xn [MM * HH];
__device__ float ws_q  [MM * HH];
__device__ float ws_k  [MM * HH];
__device__ float ws_v  [MM * HH];
__device__ float ws_x  [MM * HH];
__device__ float ws_z  [MM * HH];
__device__ float ws_ctx[MM * HH];
__device__ float ws_h  [MM * FF];
// pre-split tf32 (hi,lo) operand buffers
__device__ uint2 ws_sa [MM * FF];      // A-side (largest: FFN hidden 32M elems)
__device__ uint2 ws_sb [FF * HH];      // B-side (largest weight: 4M elems)

// ---------------------------------------------------------------------------
// Split kernel: x -> (tf32_hi, tf32_lo) interleaved uint2. 4 floats/thread.
// n must be divisible by 1024.
// ---------------------------------------------------------------------------
__device__ __forceinline__ void split1(float x, uint32_t& hi, uint32_t& lo) {
    asm("cvt.rna.tf32.f32 %0, %1;" : "=r"(hi) : "f"(x));
    float r = x - __uint_as_float(hi);
    asm("cvt.rna.tf32.f32 %0, %1;" : "=r"(lo) : "f"(r));
}

__global__ __launch_bounds__(256)
void split_kernel(const float* __restrict__ x, uint2* __restrict__ y)
{
    const int i = blockIdx.x * 256 + threadIdx.x;
    float4 v = ((const float4*)x)[i];
    uint32_t h0,l0,h1,l1,h2,l2,h3,l3;
    split1(v.x, h0, l0); split1(v.y, h1, l1);
    split1(v.z, h2, l2); split1(v.w, h3, l3);
    uint4* o = (uint4*)(y + (long long)i * 4);
    o[0] = make_uint4(h0, l0, h1, l1);
    o[1] = make_uint4(h2, l2, h3, l3);
}

// ---------------------------------------------------------------------------
// tf32x3 tensor-core GEMM on PRE-SPLIT operands:
//   C = A[M,K] @ B[N,K]^T  (+ bias/relu/resid),  A,B as uint2 (hi,lo) pairs.
// CTA tile 128x128, 8 warps (2x4), warp tile 64x32, K-chunk 16,
// cp.async double-buffered smem (uint2, row stride 20 -> conflict-free LDS.64).
// Requires: M,N % 128 == 0, K % 16 == 0; operand leading dim = K.
// ---------------------------------------------------------------------------
#define SROW 20
#define GEMM_SMEM (2 * 2 * 128 * SROW * 8)   // bufs*ops*128*SROW uint2 = 80 KB

__device__ __forceinline__ void mma_tf32(float* c, const uint32_t* a, const uint32_t* b) {
    asm volatile(
        "mma.sync.aligned.m16n8k8.row.col.f32.tf32.tf32.f32 "
        "{%0,%1,%2,%3},{%4,%5,%6,%7},{%8,%9},{%0,%1,%2,%3};"
        : "+f"(c[0]), "+f"(c[1]), "+f"(c[2]), "+f"(c[3])
        : "r"(a[0]), "r"(a[1]), "r"(a[2]), "r"(a[3]), "r"(b[0]), "r"(b[1]));
}

__device__ __forceinline__ void cp_async16(uint32_t smem_addr, const void* gptr) {
    asm volatile("cp.async.cg.shared.global [%0], [%1], 16;"
                 :: "r"(smem_addr), "l"(gptr));
}

__global__ __launch_bounds__(256, 2)
void gemm_tf32p_kernel(const uint2* __restrict__ A,
                       const uint2* __restrict__ B,
                       float*       __restrict__ C, int ldc,
                       int M, int N, int K,
                       const float* __restrict__ bias,
                       const float* __restrict__ resid, int ldres,
                       int relu)
{
    extern __shared__ uint2 smu[];
    uint2* As = smu;                       // [2][128][SROW]
    uint2* Bs = smu + 2 * 128 * SROW;      // [2][128][SROW]

    const int tid  = threadIdx.x;
    const int warp = tid >> 5;
    const int lane = tid & 31;
    const int wm = warp >> 2;              // 0..1
    const int wn = warp & 3;               // 0..3
    const int qr = lane >> 2;              // 0..7
    const int qc = lane & 3;               // 0..3
    const int m0 = blockIdx.y * 128;
    const int n0 = blockIdx.x * 128;

    const uint32_t sAu = (uint32_t)__cvta_generic_to_shared(As);
    const uint32_t sBu = (uint32_t)__cvta_generic_to_shared(Bs);

    float acc[4][4][4];
    #pragma unroll
    for (int mt = 0; mt < 4; ++mt)
        #pragma unroll
        for (int nt = 0; nt < 4; ++nt)
            #pragma unroll
            for (int r = 0; r < 4; ++r) acc[mt][nt][r] = 0.f;

    // chunk copy: 128 rows x 16 uint2 = 128B/row, 8 x 16B granules per row,
    // 1024 granules per op, 4 per thread.
    auto issue = [&](int buf, int kk0) {
        #pragma unroll
        for (int i = 0; i < 4; ++i) {
            const int idx = i * 256 + tid;
            const int row = idx >> 3;
            const int g   = idx & 7;
            const uint32_t soff = (uint32_t)(((buf * 128 + row) * SROW + g * 2) * 8);
            cp_async16(sAu + soff, A + (long long)(m0 + row) * K + kk0 + g * 2);
            cp_async16(sBu + soff, B + (long long)(n0 + row) * K + kk0 + g * 2);
        }
        asm volatile("cp.async.commit_group;");
    };

    const int nchunks = K >> 4;            // K / 16

    issue(0, 0);
    asm volatile("cp.async.wait_group 0;");
    __syncthreads();

    for (int t = 0; t < nchunks; ++t) {
        const int buf = t & 1;
        if (t + 1 < nchunks) issue(buf ^ 1, (t + 1) * 16);

        const uint2* Ab = As + buf * 128 * SROW;
        const uint2* Bb = Bs + buf * 128 * SROW;

        #pragma unroll
        for (int k8 = 0; k8 < 2; ++k8) {
            const int k0 = k8 * 8;
            uint32_t bh[4][2], bl[4][2];
            #pragma unroll
            for (int nt = 0; nt < 4; ++nt) {
                const uint2* bp = Bb + (wn * 32 + nt * 8 + qr) * SROW + k0 + qc;
                uint2 u0 = bp[0];
                uint2 u1 = bp[4];
                bh[nt][0] = u0.x; bl[nt][0] = u0.y;
                bh[nt][1] = u1.x; bl[nt][1] = u1.y;
            }
            #pragma unroll
            for (int mt = 0; mt < 4; ++mt) {
                const uint2* ap = Ab + (wm * 64 + mt * 16 + qr) * SROW + k0 + qc;
                uint2 u0 = ap[0];
                uint2 u1 = ap[8 * SROW];
                uint2 u2 = ap[4];
                uint2 u3 = ap[8 * SROW + 4];
                uint32_t ah[4] = {u0.x, u1.x, u2.x, u3.x};
                uint32_t al[4] = {u0.y, u1.y, u2.y, u3.y};
                #pragma unroll
                for (int nt = 0; nt < 4; ++nt) {
                    mma_tf32(acc[mt][nt], ah, bh[nt]);   // Ah*Bh
                    mma_tf32(acc[mt][nt], ah, bl[nt]);   // Ah*Bl
                    mma_tf32(acc[mt][nt], al, bh[nt]);   // Al*Bh
                }
            }
        }

        if (t + 1 < nchunks) {
            asm volatile("cp.async.wait_group 0;");
            __syncthreads();
        }
    }

    // Epilogue: frag -> rows qr,+8 ; cols 2*qc,+1. float2 stores.
    #pragma unroll
    for (int mt = 0; mt < 4; ++mt) {
        const int row0 = m0 + wm * 64 + mt * 16 + qr;
        #pragma unroll
        for (int nt = 0; nt < 4; ++nt) {
            const int col = n0 + wn * 32 + nt * 8 + qc * 2;
            float2 v0 = make_float2(acc[mt][nt][0], acc[mt][nt][1]);
            float2 v1 = make_float2(acc[mt][nt][2], acc[mt][nt][3]);
            if (bias) {
                float2 b2 = *(const float2*)(bias + col);
                v0.x += b2.x; v0.y += b2.y;
                v1.x += b2.x; v1.y += b2.y;
            }
            if (relu) {
                v0.x = fmaxf(v0.x, 0.f); v0.y = fmaxf(v0.y, 0.f);
                v1.x = fmaxf(v1.x, 0.f); v1.y = fmaxf(v1.y, 0.f);
            }
            if (resid) {
                float2 r0 = *(const float2*)(resid + (long long)row0 * ldres + col);
                float2 r1 = *(const float2*)(resid + (long long)(row0 + 8) * ldres + col);
                v0.x += r0.x; v0.y += r0.y;
                v1.x += r1.x; v1.y += r1.y;
            }
            *(float2*)(C + (long long)row0 * ldc + col)       = v0;
            *(float2*)(C + (long long)(row0 + 8) * ldc + col) = v1;
        }
    }
}

// ---------------------------------------------------------------------------
// Flash attention (fp32, DK=128) — unchanged (passing since R4).
// ---------------------------------------------------------------------------
#define BQ 64
#define BK 32
#define SPAD 132
#define FLASH_SMEM ((BQ*SPAD + 2*BK*SPAD + BQ*BK) * 4)

__global__ __launch_bounds__(256)
void flash_attn_kernel(const float* __restrict__ Qg, const float* __restrict__ Kg,
                       const float* __restrict__ Vg, float* __restrict__ Og,
                       int Tk, int causal)
{
    extern __shared__ float sm[];
    float* sQ = sm;
    float* sK = sQ + BQ * SPAD;
    float* sV = sK + BK * SPAD;
    float* sP = sV + BK * SPAD;

    const int tid = threadIdx.x;
    const int tx = tid & 15, ty = tid >> 4;
    const int q0 = blockIdx.x * BQ;
    const int bh = blockIdx.y;
    const int bb = bh >> 3, hh = bh & 7;

    const float* Qp = Qg + ((long long)(bb * TT + q0)) * HH + hh * DKK;
    const float* Kp = Kg + ((long long)bb * Tk) * HH + hh * DKK;
    const float* Vp = Vg + ((long long)bb * Tk) * HH + hh * DKK;

    #pragma unroll
    for (int i = 0; i < 8; ++i) {
        int f = i * 256 + tid;
        int row = f >> 5, c4 = (f & 31) * 4;
        *(float4*)&sQ[row * SPAD + c4] = *(const float4*)(Qp + (long long)row * HH + c4);
    }

    const float scale = 0.08838834764831845f;
    float m[4], l[4], o[4][8];
    #pragma unroll
    for (int i = 0; i < 4; ++i) {
        m[i] = -INFINITY; l[i] = 0.f;
        #pragma unroll
        for (int c = 0; c < 8; ++c) o[i][c] = 0.f;
    }

    const int nkt = causal ? (q0 / BK + 2) : (Tk / BK);

    for (int kt = 0; kt < nkt; ++kt) {
        __syncthreads();
        const long long krow0 = (long long)kt * BK;
        #pragma unroll
        for (int i = 0; i < 4; ++i) {
            int f = i * 256 + tid;
            int row = f >> 5, c4 = (f & 31) * 4;
            *(float4*)&sK[row * SPAD + c4] = *(const float4*)(Kp + (krow0 + row) * HH + c4);
            *(float4*)&sV[row * SPAD + c4] = *(const float4*)(Vp + (krow0 + row) * HH + c4);
        }
        __syncthreads();

        float s[4][2];
        #pragma unroll
        for (int i = 0; i < 4; ++i) { s[i][0] = 0.f; s[i][1] = 0.f; }
        #pragma unroll 4
        for (int d = 0; d < DKK; d += 4) {
            float4 kv0 = *(const float4*)&sK[(tx     ) * SPAD + d];
            float4 kv1 = *(const float4*)&sK[(tx + 16) * SPAD + d];
            #pragma unroll
            for (int i = 0; i < 4; ++i) {
                float4 qv = *(const float4*)&sQ[(ty * 4 + i) * SPAD + d];
                s[i][0] += qv.x * kv0.x + qv.y * kv0.y + qv.z * kv0.z + qv.w * kv0.w;
                s[i][1] += qv.x * kv1.x + qv.y * kv1.y + qv.z * kv1.z + qv.w * kv1.w;
            }
        }

        #pragma unroll
        for (int i = 0; i < 4; ++i) {
            int qg = q0 + ty * 4 + i;
            #pragma unroll
            for (int j = 0; j < 2; ++j) {
                s[i][j] *= scale;
                if (causal && (kt * BK + tx + j * 16 > qg)) s[i][j] = -INFINITY;
            }
        }

        float corr[4];
        #pragma unroll
        for (int i = 0; i < 4; ++i) {
            float mx = fmaxf(s[i][0], s[i][1]);
            #pragma unroll
            for (int off = 8; off; off >>= 1)
                mx = fmaxf(mx, __shfl_xor_sync(0xffffffffu, mx, off));
            float mn = fmaxf(m[i], mx);
            corr[i] = __expf(m[i] - mn);
            float p0 = __expf(s[i][0] - mn);
            float p1 = __expf(s[i][1] - mn);
            float ts = p0 + p1;
            #pragma unroll
            for (int off = 8; off; off >>= 1)
                ts += __shfl_xor_sync(0xffffffffu, ts, off);
            l[i] = l[i] * corr[i] + ts;
            m[i] = mn;
            sP[(ty * 4 + i) * BK + tx     ] = p0;
            sP[(ty * 4 + i) * BK + tx + 16] = p1;
            #pragma unroll
            for (int c = 0; c < 8; ++c) o[i][c] *= corr[i];
        }
        __syncthreads();

        #pragma unroll
        for (int k4 = 0; k4 < BK; k4 += 4) {
            float4 pv[4];
            #pragma unroll
            for (int i = 0; i < 4; ++i)
                pv[i] = *(const float4*)&sP[(ty * 4 + i) * BK + k4];
            #pragma unroll
            for (int kk = 0; kk < 4; ++kk) {
                float4 v0 = *(const float4*)&sV[(k4 + kk) * SPAD + tx * 8];
                float4 v1 = *(const float4*)&sV[(k4 + kk) * SPAD + tx * 8 + 4];
                #pragma unroll
                for (int i = 0; i < 4; ++i) {
                    float p = (kk == 0) ? pv[i].x : (kk == 1) ? pv[i].y
                            : (kk == 2) ? pv[i].z : pv[i].w;
                    o[i][0] += p * v0.x; o[i][1] += p * v0.y;
                    o[i][2] += p * v0.z; o[i][3] += p * v0.w;
                    o[i][4] += p * v1.x; o[i][5] += p * v1.y;
                    o[i][6] += p * v1.z; o[i][7] += p * v1.w;
                }
            }
        }
    }

    #pragma unroll
    for (int i = 0; i < 4; ++i) {
        float inv = 1.f / l[i];
        float4 r0, r1;
        r0.x = o[i][0] * inv; r0.y = o[i][1] * inv;
        r0.z = o[i][2] * inv; r0.w = o[i][3] * inv;
        r1.x = o[i][4] * inv; r1.y = o[i][5] * inv;
        r1.z = o[i][6] * inv; r1.w = o[i][7] * inv;
        float* op = Og + ((long long)(bb * TT + q0 + ty * 4 + i)) * HH + hh * DKK + tx * 8;
        *(float4*)op = r0;
        *(float4*)(op + 4) = r1;
    }
}

// ---------------------------------------------------------------------------
// LayerNorm over last dim (1024). One block (256 threads) per row.
// ---------------------------------------------------------------------------
__global__ __launch_bounds__(256)
void layernorm_kernel(const float* __restrict__ x, const float* __restrict__ g,
                      const float* __restrict__ b, float* __restrict__ y)
{
    const long long row = blockIdx.x;
    const int tid = threadIdx.x;
    float4 v = ((const float4*)(x + row * HH))[tid];

    __shared__ float red[8];
    float s = v.x + v.y + v.z + v.w;
    #pragma unroll
    for (int o = 16; o; o >>= 1) s += __shfl_xor_sync(0xffffffffu, s, o);
    if ((tid & 31) == 0) red[tid >> 5] = s;
    __syncthreads();
    float mean = (red[0] + red[1] + red[2] + red[3] +
                  red[4] + red[5] + red[6] + red[7]) * (1.f / HH);
    __syncthreads();

    float dx = v.x - mean, dy = v.y - mean, dz = v.z - mean, dw = v.w - mean;
    float sq = dx * dx + dy * dy + dz * dz + dw * dw;
    #pragma unroll
    for (int o = 16; o; o >>= 1) sq += __shfl_xor_sync(0xffffffffu, sq, o);
    if ((tid & 31) == 0) red[tid >> 5] = sq;
    __syncthreads();
    float var = (red[0] + red[1] + red[2] + red[3] +
                 red[4] + red[5] + red[6] + red[7]) * (1.f / HH);
    float rstd = rsqrtf(var + 1e-5f);

    float4 g4 = ((const float4*)g)[tid];
    float4 b4 = ((const float4*)b)[tid];
    float4 o4;
    o4.x = dx * rstd * g4.x + b4.x;
    o4.y = dy * rstd * g4.y + b4.y;
    o4.z = dz * rstd * g4.z + b4.z;
    o4.w = dw * rstd * g4.w + b4.w;
    ((float4*)(y + row * HH))[tid] = o4;
}

// ---------------------------------------------------------------------------
// Host orchestration
// ---------------------------------------------------------------------------
extern "C" void kernel_launch(void* const* d_in, const int* in_sizes, int n_in,
                              void* d_out, int out_size)
{
    const float* input_ = (const float*)d_in[0];
    const float* enc    = (const float*)d_in[1];
    const float* Wq_s = (const float*)d_in[4];
    const float* Wk_s = (const float*)d_in[5];
    const float* Wv_s = (const float*)d_in[6];
    const float* Wo_s = (const float*)d_in[7];
    const float* Wq_c = (const float*)d_in[8];
    const float* Wk_c = (const float*)d_in[9];
    const float* Wv_c = (const float*)d_in[10];
    const float* Wo_c = (const float*)d_in[11];
    const float* w1   = (const float*)d_in[12];
    const float* b1   = (const float*)d_in[13];
    const float* w2   = (const float*)d_in[14];
    const float* b2   = (const float*)d_in[15];
    const float* g_mmha = (const float*)d_in[16];
    const float* b_mmha = (const float*)d_in[17];
    const float* g_mha  = (const float*)d_in[18];
    const float* b_mha  = (const float*)d_in[19];
    const float* g_ffn  = (const float*)d_in[20];
    const float* b_ffn  = (const float*)d_in[21];
    float* out = (float*)d_out;

    float *xn, *q, *k, *v, *x, *z, *ctx, *hbuf;
    uint2 *sa, *sb;
    cudaGetSymbolAddress((void**)&xn,   ws_xn);
    cudaGetSymbolAddress((void**)&q,    ws_q);
    cudaGetSymbolAddress((void**)&k,    ws_k);
    cudaGetSymbolAddress((void**)&v,    ws_v);
    cudaGetSymbolAddress((void**)&x,    ws_x);
    cudaGetSymbolAddress((void**)&z,    ws_z);
    cudaGetSymbolAddress((void**)&ctx,  ws_ctx);
    cudaGetSymbolAddress((void**)&hbuf, ws_h);
    cudaGetSymbolAddress((void**)&sa,   ws_sa);
    cudaGetSymbolAddress((void**)&sb,   ws_sb);

    cudaFuncSetAttribute(flash_attn_kernel,
                         cudaFuncAttributeMaxDynamicSharedMemorySize, FLASH_SMEM);
    cudaFuncSetAttribute(gemm_tf32p_kernel,
                         cudaFuncAttributeMaxDynamicSharedMemorySize, GEMM_SMEM);

    auto split = [&](const float* src, uint2* dst, long long n) {
        split_kernel<<<(int)(n / 1024), 256>>>(src, dst);
    };
    // C = A @ W^T on tensor cores; operands already split in sa/sb
    auto gemm = [&](float* C, int M, int N, int K,
                    const float* bias, const float* resid, int relu) {
        dim3 grid(N / 128, M / 128, 1);
        gemm_tf32p_kernel<<<grid, 256, GEMM_SMEM>>>(sa, sb, C, N, M, N, K,
                                                    bias, resid, N, relu);
    };
    auto flash = [&](const float* Q, const float* K, const float* V, float* O,
                     int Tk, int causal) {
        dim3 grid(TT / BQ, BB * NHH);
        flash_attn_kernel<<<grid, 256, FLASH_SMEM>>>(Q, K, V, O, Tk, causal);
    };

    const long long nMH = (long long)MM * HH;   // 8M elems
    const long long nW  = (long long)HH * HH;   // 1M elems
    const long long nW1 = (long long)FF * HH;   // 4M elems

    // ---- self attention ----
    layernorm_kernel<<<MM, 256>>>(input_, g_mmha, b_mmha, xn);
    split(xn, sa, nMH);
    split(Wq_s, sb, nW);  gemm(q, MM, HH, HH, nullptr, nullptr, 0);
    split(Wk_s, sb, nW);  gemm(k, MM, HH, HH, nullptr, nullptr, 0);
    split(Wv_s, sb, nW);  gemm(v, MM, HH, HH, nullptr, nullptr, 0);
    flash(q, k, v, ctx, TT, /*causal=*/1);
    split(ctx, sa, nMH);
    split(Wo_s, sb, nW);  gemm(x, MM, HH, HH, nullptr, input_, 0);

    // ---- cross attention ----
    layernorm_kernel<<<MM, 256>>>(x, g_mha, b_mha, xn);
    split(xn, sa, nMH);
    split(Wq_c, sb, nW);  gemm(q, MM, HH, HH, nullptr, nullptr, 0);
    split(enc, sa, nMH);
    split(Wk_c, sb, nW);  gemm(k, BB * TEE, HH, HH, nullptr, nullptr, 0);
    split(Wv_c, sb, nW);  gemm(v, BB * TEE, HH, HH, nullptr, nullptr, 0);
    flash(q, k, v, ctx, TEE, /*causal=*/0);
    split(ctx, sa, nMH);
    split(Wo_c, sb, nW);  gemm(z, MM, HH, HH, nullptr, x, 0);

    // ---- FFN ----
    layernorm_kernel<<<MM, 256>>>(z, g_ffn, b_ffn, xn);
    split(xn, sa, nMH);
    split(w1, sb, nW1);   gemm(hbuf, MM, FF, HH, b1, nullptr, 1);
    split(hbuf, sa, (long long)MM * FF);
    split(w2, sb, nW1);   gemm(out, MM, HH, FF, b2, z, 0);
}

// round 7
// speedup vs baseline: 1.6788x; 1.6788x over previous
#include <cuda_runtime.h>
#include <cuda_bf16.h>
#include <math.h>
#include <stdint.h>

// Problem constants (fixed by the reference setup)
#define BB   8
#define TT   1024
#define TEE  1024
#define HH   1024
#define NHH  8
#define DKK  128
#define MM   (BB * TT)       // 8192 rows
#define FF   4096            // FFN hidden

// ---------------------------------------------------------------------------
// Scratch (static device globals)
// ---------------------------------------------------------------------------
__device__ float ws_q  [MM * HH];
__device__ float ws_k  [MM * HH];
__device__ float ws_v  [MM * HH];
__device__ float ws_x  [MM * HH];
__device__ float ws_z  [MM * HH];
// bf16 hi/lo operand planes
__device__ __nv_bfloat16 ws_ah [MM * HH];   // A-side planes (LN out / ctx / enc)
__device__ __nv_bfloat16 ws_al [MM * HH];
__device__ __nv_bfloat16 ws_hh [MM * FF];   // FFN hidden planes
__device__ __nv_bfloat16 ws_hl [MM * FF];
__device__ __nv_bfloat16 ws_bh [FF * HH];   // B-side (weight) planes
__device__ __nv_bfloat16 ws_bl [FF * HH];

// ---------------------------------------------------------------------------
// bf16 hi/lo split helpers
// ---------------------------------------------------------------------------
__device__ __forceinline__ void split_bf(float x, __nv_bfloat16& hi, __nv_bfloat16& lo) {
    hi = __float2bfloat16_rn(x);
    lo = __float2bfloat16_rn(x - __bfloat162float(hi));
}

// standalone split: 4 floats/thread; n % 1024 == 0
__global__ __launch_bounds__(256)
void split_kernel(const float* __restrict__ x,
                  __nv_bfloat16* __restrict__ hi, __nv_bfloat16* __restrict__ lo)
{
    const long long i = (long long)blockIdx.x * 256 + threadIdx.x;
    float4 v = ((const float4*)x)[i];
    __nv_bfloat16 h[4], l[4];
    split_bf(v.x, h[0], l[0]); split_bf(v.y, h[1], l[1]);
    split_bf(v.z, h[2], l[2]); split_bf(v.w, h[3], l[3]);
    __nv_bfloat162* hp = (__nv_bfloat162*)(hi + i * 4);
    __nv_bfloat162* lp = (__nv_bfloat162*)(lo + i * 4);
    hp[0] = __nv_bfloat162(h[0], h[1]); hp[1] = __nv_bfloat162(h[2], h[3]);
    lp[0] = __nv_bfloat162(l[0], l[1]); lp[1] = __nv_bfloat162(l[2], l[3]);
}

// ---------------------------------------------------------------------------
// bf16x3 tensor-core GEMM:  C = A[M,K] @ B[N,K]^T  (+ bias/relu/resid)
// A,B given as hi/lo bf16 planes. 3 MMAs (AhBh + AhBl + AlBh) per m16n8k16.
// CTA tile 128x128, 8 warps (2x4), warp tile 64x32, K-chunk 32,
// cp.async double-buffered smem; row stride 40 bf16 (80B) -> conflict-free
// 4B fragment loads. Output: fp32 C, or hi/lo planes (Chi/Clo non-null).
// Requires: M,N % 128 == 0, K % 32 == 0.
// ---------------------------------------------------------------------------
#define SROW 40                          // bf16 elems per smem row (32 data + 8 pad)
#define PLANE (128 * SROW)               // 5120 bf16 per plane
#define BUFSZ (4 * PLANE)                // Ah,Al,Bh,Bl
#define GEMM_SMEM (2 * BUFSZ * 2)        // 2 bufs, bytes = 81920

__device__ __forceinline__ void mma_bf16(float* c, const uint32_t* a, const uint32_t* b) {
    asm volatile(
        "mma.sync.aligned.m16n8k16.row.col.f32.bf16.bf16.f32 "
        "{%0,%1,%2,%3},{%4,%5,%6,%7},{%8,%9},{%0,%1,%2,%3};"
        : "+f"(c[0]), "+f"(c[1]), "+f"(c[2]), "+f"(c[3])
        : "r"(a[0]), "r"(a[1]), "r"(a[2]), "r"(a[3]), "r"(b[0]), "r"(b[1]));
}

__device__ __forceinline__ void cp_async16(uint32_t smem_addr, const void* gptr) {
    asm volatile("cp.async.cg.shared.global [%0], [%1], 16;"
                 :: "r"(smem_addr), "l"(gptr));
}

__global__ __launch_bounds__(256, 2)
void gemm_bf16x3_kernel(const __nv_bfloat16* __restrict__ Ah,
                        const __nv_bfloat16* __restrict__ Al,
                        const __nv_bfloat16* __restrict__ Bh,
                        const __nv_bfloat16* __restrict__ Bl,
                        float* __restrict__ C,
                        __nv_bfloat16* __restrict__ Chi,
                        __nv_bfloat16* __restrict__ Clo,
                        int ldc, int M, int N, int K,
                        const float* __restrict__ bias,
                        const float* __restrict__ resid, int ldres,
                        int relu)
{
    extern __shared__ __nv_bfloat16 smb[];

    const int tid  = threadIdx.x;
    const int warp = tid >> 5;
    const int lane = tid & 31;
    const int wm = warp >> 2;              // 0..1
    const int wn = warp & 3;               // 0..3
    const int qr = lane >> 2;              // 0..7
    const int qc = lane & 3;               // 0..3
    const int m0 = blockIdx.y * 128;
    const int n0 = blockIdx.x * 128;

    const uint32_t sbase = (uint32_t)__cvta_generic_to_shared(smb);

    float acc[4][4][4];
    #pragma unroll
    for (int mt = 0; mt < 4; ++mt)
        #pragma unroll
        for (int nt = 0; nt < 4; ++nt)
            #pragma unroll
            for (int r = 0; r < 4; ++r) acc[mt][nt][r] = 0.f;

    // copy: per op-plane 128 rows x 4 granules (16B = 8 bf16); 2048 total, 8/thread
    auto issue = [&](int buf, int kk0) {
        #pragma unroll
        for (int i = 0; i < 8; ++i) {
            const int op   = i >> 1;                       // compile-time
            const int widx = (i & 1) * 256 + tid;          // 0..511
            const int row  = widx >> 2;
            const int g    = widx & 3;
            const __nv_bfloat16* src;
            if      (op == 0) src = Ah + (long long)(m0 + row) * K + kk0 + g * 8;
            else if (op == 1) src = Al + (long long)(m0 + row) * K + kk0 + g * 8;
            else if (op == 2) src = Bh + (long long)(n0 + row) * K + kk0 + g * 8;
            else              src = Bl + (long long)(n0 + row) * K + kk0 + g * 8;
            const uint32_t soff = (uint32_t)((buf * BUFSZ + op * PLANE + row * SROW + g * 8) * 2);
            cp_async16(sbase + soff, src);
        }
        asm volatile("cp.async.commit_group;");
    };

    const int nchunks = K >> 5;            // K / 32

    issue(0, 0);
    asm volatile("cp.async.wait_group 0;");
    __syncthreads();

    for (int t = 0; t < nchunks; ++t) {
        const int buf = t & 1;
        if (t + 1 < nchunks) issue(buf ^ 1, (t + 1) * 32);

        const __nv_bfloat16* sAh = smb + buf * BUFSZ;
        const __nv_bfloat16* sAl = sAh + PLANE;
        const __nv_bfloat16* sBh = sAl + PLANE;
        const __nv_bfloat16* sBl = sBh + PLANE;

        #pragma unroll
        for (int ks = 0; ks < 2; ++ks) {
            const int k0 = ks * 16;        // bf16 elems into the 32-wide chunk
            // B fragments (hi/lo), 4 n-tiles
            uint32_t bh[4][2], bl[4][2];
            #pragma unroll
            for (int nt = 0; nt < 4; ++nt) {
                const int r = (wn * 32 + nt * 8 + qr) * SROW + k0 + qc * 2;
                bh[nt][0] = *(const uint32_t*)(sBh + r);
                bh[nt][1] = *(const uint32_t*)(sBh + r + 8);
                bl[nt][0] = *(const uint32_t*)(sBl + r);
                bl[nt][1] = *(const uint32_t*)(sBl + r + 8);
            }
            #pragma unroll
            for (int mt = 0; mt < 4; ++mt) {
                const int r = (wm * 64 + mt * 16 + qr) * SROW + k0 + qc * 2;
                uint32_t ah[4], al[4];
                ah[0] = *(const uint32_t*)(sAh + r);
                ah[1] = *(const uint32_t*)(sAh + r + 8 * SROW);
                ah[2] = *(const uint32_t*)(sAh + r + 8);
                ah[3] = *(const uint32_t*)(sAh + r + 8 * SROW + 8);
                al[0] = *(const uint32_t*)(sAl + r);
                al[1] = *(const uint32_t*)(sAl + r + 8 * SROW);
                al[2] = *(const uint32_t*)(sAl + r + 8);
                al[3] = *(const uint32_t*)(sAl + r + 8 * SROW + 8);
                #pragma unroll
                for (int nt = 0; nt < 4; ++nt) {
                    mma_bf16(acc[mt][nt], ah, bh[nt]);   // Ah*Bh
                    mma_bf16(acc[mt][nt], ah, bl[nt]);   // Ah*Bl
                    mma_bf16(acc[mt][nt], al, bh[nt]);   // Al*Bh
                }
            }
        }

        if (t + 1 < nchunks) {
            asm volatile("cp.async.wait_group 0;");
            __syncthreads();
        }
    }

    // Epilogue: frag -> rows qr,+8 ; cols 2*qc,+1.
    #pragma unroll
    for (int mt = 0; mt < 4; ++mt) {
        const int row0 = m0 + wm * 64 + mt * 16 + qr;
        #pragma unroll
        for (int nt = 0; nt < 4; ++nt) {
            const int col = n0 + wn * 32 + nt * 8 + qc * 2;
            float2 v0 = make_float2(acc[mt][nt][0], acc[mt][nt][1]);
            float2 v1 = make_float2(acc[mt][nt][2], acc[mt][nt][3]);
            if (bias) {
                float2 b2 = *(const float2*)(bias + col);
                v0.x += b2.x; v0.y += b2.y;
                v1.x += b2.x; v1.y += b2.y;
            }
            if (relu) {
                v0.x = fmaxf(v0.x, 0.f); v0.y = fmaxf(v0.y, 0.f);
                v1.x = fmaxf(v1.x, 0.f); v1.y = fmaxf(v1.y, 0.f);
            }
            if (resid) {
                float2 r0 = *(const float2*)(resid + (long long)row0 * ldres + col);
                float2 r1 = *(const float2*)(resid + (long long)(row0 + 8) * ldres + col);
                v0.x += r0.x; v0.y += r0.y;
                v1.x += r1.x; v1.y += r1.y;
            }
            if (Chi) {
                __nv_bfloat16 h0a,l0a,h0b,l0b,h1a,l1a,h1b,l1b;
                split_bf(v0.x, h0a, l0a); split_bf(v0.y, h0b, l0b);
                split_bf(v1.x, h1a, l1a); split_bf(v1.y, h1b, l1b);
                *(__nv_bfloat162*)(Chi + (long long)row0 * ldc + col)       = __nv_bfloat162(h0a, h0b);
                *(__nv_bfloat162*)(Clo + (long long)row0 * ldc + col)       = __nv_bfloat162(l0a, l0b);
                *(__nv_bfloat162*)(Chi + (long long)(row0 + 8) * ldc + col) = __nv_bfloat162(h1a, h1b);
                *(__nv_bfloat162*)(Clo + (long long)(row0 + 8) * ldc + col) = __nv_bfloat162(l1a, l1b);
            } else {
                *(float2*)(C + (long long)row0 * ldc + col)       = v0;
                *(float2*)(C + (long long)(row0 + 8) * ldc + col) = v1;
            }
        }
    }
}

// ---------------------------------------------------------------------------
// Flash attention (fp32, DK=128). Epilogue writes bf16 hi/lo planes.
// ---------------------------------------------------------------------------
#define BQ 64
#define BK 32
#define SPAD 132
#define FLASH_SMEM ((BQ*SPAD + 2*BK*SPAD + BQ*BK) * 4)

__global__ __launch_bounds__(256)
void flash_attn_kernel(const float* __restrict__ Qg, const float* __restrict__ Kg,
                       const float* __restrict__ Vg,
                       __nv_bfloat16* __restrict__ Ohi, __nv_bfloat16* __restrict__ Olo,
                       int Tk, int causal)
{
    extern __shared__ float sm[];
    float* sQ = sm;
    float* sK = sQ + BQ * SPAD;
    float* sV = sK + BK * SPAD;
    float* sP = sV + BK * SPAD;

    const int tid = threadIdx.x;
    const int tx = tid & 15, ty = tid >> 4;
    const int q0 = blockIdx.x * BQ;
    const int bh = blockIdx.y;
    const int bb = bh >> 3, hh = bh & 7;

    const float* Qp = Qg + ((long long)(bb * TT + q0)) * HH + hh * DKK;
    const float* Kp = Kg + ((long long)bb * Tk) * HH + hh * DKK;
    const float* Vp = Vg + ((long long)bb * Tk) * HH + hh * DKK;

    #pragma unroll
    for (int i = 0; i < 8; ++i) {
        int f = i * 256 + tid;
        int row = f >> 5, c4 = (f & 31) * 4;
        *(float4*)&sQ[row * SPAD + c4] = *(const float4*)(Qp + (long long)row * HH + c4);
    }

    const float scale = 0.08838834764831845f;
    float m[4], l[4], o[4][8];
    #pragma unroll
    for (int i = 0; i < 4; ++i) {
        m[i] = -INFINITY; l[i] = 0.f;
        #pragma unroll
        for (int c = 0; c < 8; ++c) o[i][c] = 0.f;
    }

    const int nkt = causal ? (q0 / BK + 2) : (Tk / BK);

    for (int kt = 0; kt < nkt; ++kt) {
        __syncthreads();
        const long long krow0 = (long long)kt * BK;
        #pragma unroll
        for (int i = 0; i < 4; ++i) {
            int f = i * 256 + tid;
            int row = f >> 5, c4 = (f & 31) * 4;
            *(float4*)&sK[row * SPAD + c4] = *(const float4*)(Kp + (krow0 + row) * HH + c4);
            *(float4*)&sV[row * SPAD + c4] = *(const float4*)(Vp + (krow0 + row) * HH + c4);
        }
        __syncthreads();

        float s[4][2];
        #pragma unroll
        for (int i = 0; i < 4; ++i) { s[i][0] = 0.f; s[i][1] = 0.f; }
        #pragma unroll 4
        for (int d = 0; d < DKK; d += 4) {
            float4 kv0 = *(const float4*)&sK[(tx     ) * SPAD + d];
            float4 kv1 = *(const float4*)&sK[(tx + 16) * SPAD + d];
            #pragma unroll
            for (int i = 0; i < 4; ++i) {
                float4 qv = *(const float4*)&sQ[(ty * 4 + i) * SPAD + d];
                s[i][0] += qv.x * kv0.x + qv.y * kv0.y + qv.z * kv0.z + qv.w * kv0.w;
                s[i][1] += qv.x * kv1.x + qv.y * kv1.y + qv.z * kv1.z + qv.w * kv1.w;
            }
        }

        #pragma unroll
        for (int i = 0; i < 4; ++i) {
            int qg = q0 + ty * 4 + i;
            #pragma unroll
            for (int j = 0; j < 2; ++j) {
                s[i][j] *= scale;
                if (causal && (kt * BK + tx + j * 16 > qg)) s[i][j] = -INFINITY;
            }
        }

        float corr[4];
        #pragma unroll
        for (int i = 0; i < 4; ++i) {
            float mx = fmaxf(s[i][0], s[i][1]);
            #pragma unroll
            for (int off = 8; off; off >>= 1)
                mx = fmaxf(mx, __shfl_xor_sync(0xffffffffu, mx, off));
            float mn = fmaxf(m[i], mx);
            corr[i] = __expf(m[i] - mn);
            float p0 = __expf(s[i][0] - mn);
            float p1 = __expf(s[i][1] - mn);
            float ts = p0 + p1;
            #pragma unroll
            for (int off = 8; off; off >>= 1)
                ts += __shfl_xor_sync(0xffffffffu, ts, off);
            l[i] = l[i] * corr[i] + ts;
            m[i] = mn;
            sP[(ty * 4 + i) * BK + tx     ] = p0;
            sP[(ty * 4 + i) * BK + tx + 16] = p1;
            #pragma unroll
            for (int c = 0; c < 8; ++c) o[i][c] *= corr[i];
        }
        __syncthreads();

        #pragma unroll
        for (int k4 = 0; k4 < BK; k4 += 4) {
            float4 pv[4];
            #pragma unroll
            for (int i = 0; i < 4; ++i)
                pv[i] = *(const float4*)&sP[(ty * 4 + i) * BK + k4];
            #pragma unroll
            for (int kk = 0; kk < 4; ++kk) {
                float4 v0 = *(const float4*)&sV[(k4 + kk) * SPAD + tx * 8];
                float4 v1 = *(const float4*)&sV[(k4 + kk) * SPAD + tx * 8 + 4];
                #pragma unroll
                for (int i = 0; i < 4; ++i) {
                    float p = (kk == 0) ? pv[i].x : (kk == 1) ? pv[i].y
                            : (kk == 2) ? pv[i].z : pv[i].w;
                    o[i][0] += p * v0.x; o[i][1] += p * v0.y;
                    o[i][2] += p * v0.z; o[i][3] += p * v0.w;
                    o[i][4] += p * v1.x; o[i][5] += p * v1.y;
                    o[i][6] += p * v1.z; o[i][7] += p * v1.w;
                }
            }
        }
    }

    #pragma unroll
    for (int i = 0; i < 4; ++i) {
        float inv = 1.f / l[i];
        __nv_bfloat16 h[8], lo[8];
        #pragma unroll
        for (int c = 0; c < 8; ++c) split_bf(o[i][c] * inv, h[c], lo[c]);
        long long off = ((long long)(bb * TT + q0 + ty * 4 + i)) * HH + hh * DKK + tx * 8;
        __nv_bfloat162* hp = (__nv_bfloat162*)(Ohi + off);
        __nv_bfloat162* lp = (__nv_bfloat162*)(Olo + off);
        hp[0] = __nv_bfloat162(h[0], h[1]);  hp[1] = __nv_bfloat162(h[2], h[3]);
        hp[2] = __nv_bfloat162(h[4], h[5]);  hp[3] = __nv_bfloat162(h[6], h[7]);
        lp[0] = __nv_bfloat162(lo[0], lo[1]); lp[1] = __nv_bfloat162(lo[2], lo[3]);
        lp[2] = __nv_bfloat162(lo[4], lo[5]); lp[3] = __nv_bfloat162(lo[6], lo[7]);
    }
}

// ---------------------------------------------------------------------------
// LayerNorm over last dim (1024); writes bf16 hi/lo planes directly.
// ---------------------------------------------------------------------------
__global__ __launch_bounds__(256)
void layernorm_split_kernel(const float* __restrict__ x, const float* __restrict__ g,
                            const float* __restrict__ b,
                            __nv_bfloat16* __restrict__ yhi,
                            __nv_bfloat16* __restrict__ ylo)
{
    const long long row = blockIdx.x;
    const int tid = threadIdx.x;
    float4 v = ((const float4*)(x + row * HH))[tid];

    __shared__ float red[8];
    float s = v.x + v.y + v.z + v.w;
    #pragma unroll
    for (int o = 16; o; o >>= 1) s += __shfl_xor_sync(0xffffffffu, s, o);
    if ((tid & 31) == 0) red[tid >> 5] = s;
    __syncthreads();
    float mean = (red[0] + red[1] + red[2] + red[3] +
                  red[4] + red[5] + red[6] + red[7]) * (1.f / HH);
    __syncthreads();

    float dx = v.x - mean, dy = v.y - mean, dz = v.z - mean, dw = v.w - mean;
    float sq = dx * dx + dy * dy + dz * dz + dw * dw;
    #pragma unroll
    for (int o = 16; o; o >>= 1) sq += __shfl_xor_sync(0xffffffffu, sq, o);
    if ((tid & 31) == 0) red[tid >> 5] = sq;
    __syncthreads();
    float var = (red[0] + red[1] + red[2] + red[3] +
                 red[4] + red[5] + red[6] + red[7]) * (1.f / HH);
    float rstd = rsqrtf(var + 1e-5f);

    float4 g4 = ((const float4*)g)[tid];
    float4 b4 = ((const float4*)b)[tid];
    float y0 = dx * rstd * g4.x + b4.x;
    float y1 = dy * rstd * g4.y + b4.y;
    float y2 = dz * rstd * g4.z + b4.z;
    float y3 = dw * rstd * g4.w + b4.w;

    __nv_bfloat16 h0,l0,h1,l1,h2,l2,h3,l3;
    split_bf(y0, h0, l0); split_bf(y1, h1, l1);
    split_bf(y2, h2, l2); split_bf(y3, h3, l3);
    __nv_bfloat162* hp = (__nv_bfloat162*)(yhi + row * HH + tid * 4);
    __nv_bfloat162* lp = (__nv_bfloat162*)(ylo + row * HH + tid * 4);
    hp[0] = __nv_bfloat162(h0, h1); hp[1] = __nv_bfloat162(h2, h3);
    lp[0] = __nv_bfloat162(l0, l1); lp[1] = __nv_bfloat162(l2, l3);
}

// ---------------------------------------------------------------------------
// Host orchestration
// ---------------------------------------------------------------------------
extern "C" void kernel_launch(void* const* d_in, const int* in_sizes, int n_in,
                              void* d_out, int out_size)
{
    const float* input_ = (const float*)d_in[0];
    const float* enc    = (const float*)d_in[1];
    const float* Wq_s = (const float*)d_in[4];
    const float* Wk_s = (const float*)d_in[5];
    const float* Wv_s = (const float*)d_in[6];
    const float* Wo_s = (const float*)d_in[7];
    const float* Wq_c = (const float*)d_in[8];
    const float* Wk_c = (const float*)d_in[9];
    const float* Wv_c = (const float*)d_in[10];
    const float* Wo_c = (const float*)d_in[11];
    const float* w1   = (const float*)d_in[12];
    const float* b1   = (const float*)d_in[13];
    const float* w2   = (const float*)d_in[14];
    const float* b2   = (const float*)d_in[15];
    const float* g_mmha = (const float*)d_in[16];
    const float* b_mmha = (const float*)d_in[17];
    const float* g_mha  = (const float*)d_in[18];
    const float* b_mha  = (const float*)d_in[19];
    const float* g_ffn  = (const float*)d_in[20];
    const float* b_ffn  = (const float*)d_in[21];
    float* out = (float*)d_out;

    float *q, *k, *v, *x, *z;
    __nv_bfloat16 *ah, *al, *hh, *hl, *bh, *bl;
    cudaGetSymbolAddress((void**)&q,  ws_q);
    cudaGetSymbolAddress((void**)&k,  ws_k);
    cudaGetSymbolAddress((void**)&v,  ws_v);
    cudaGetSymbolAddress((void**)&x,  ws_x);
    cudaGetSymbolAddress((void**)&z,  ws_z);
    cudaGetSymbolAddress((void**)&ah, ws_ah);
    cudaGetSymbolAddress((void**)&al, ws_al);
    cudaGetSymbolAddress((void**)&hh, ws_hh);
    cudaGetSymbolAddress((void**)&hl, ws_hl);
    cudaGetSymbolAddress((void**)&bh, ws_bh);
    cudaGetSymbolAddress((void**)&bl, ws_bl);

    cudaFuncSetAttribute(flash_attn_kernel,
                         cudaFuncAttributeMaxDynamicSharedMemorySize, FLASH_SMEM);
    cudaFuncSetAttribute(gemm_bf16x3_kernel,
                         cudaFuncAttributeMaxDynamicSharedMemorySize, GEMM_SMEM);

    auto split = [&](const float* src, __nv_bfloat16* h, __nv_bfloat16* l, long long n) {
        split_kernel<<<(int)(n / 1024), 256>>>(src, h, l);
    };
    // C = A @ W^T; A planes (pah,pal), B planes = (bh,bl)
    auto gemm = [&](const __nv_bfloat16* pah, const __nv_bfloat16* pal,
                    float* C, __nv_bfloat16* chi, __nv_bfloat16* clo,
                    int M, int N, int K,
                    const float* bias, const float* resid, int relu) {
        dim3 grid(N / 128, M / 128, 1);
        gemm_bf16x3_kernel<<<grid, 256, GEMM_SMEM>>>(pah, pal, bh, bl,
                                                     C, chi, clo, N, M, N, K,
                                                     bias, resid, N, relu);
    };
    auto flash = [&](const float* Q, const float* K, const float* V,
                     __nv_bfloat16* ohi, __nv_bfloat16* olo, int Tk, int causal) {
        dim3 grid(TT / BQ, BB * NHH);
        flash_attn_kernel<<<grid, 256, FLASH_SMEM>>>(Q, K, V, ohi, olo, Tk, causal);
    };

    const long long nW  = (long long)HH * HH;   // 1M elems
    const long long nW1 = (long long)FF * HH;   // 4M elems
    const long long nMH = (long long)MM * HH;   // 8M elems

    // ---- self attention ----
    layernorm_split_kernel<<<MM, 256>>>(input_, g_mmha, b_mmha, ah, al);
    split(Wq_s, bh, bl, nW);  gemm(ah, al, q, 0, 0, MM, HH, HH, nullptr, nullptr, 0);
    split(Wk_s, bh, bl, nW);  gemm(ah, al, k, 0, 0, MM, HH, HH, nullptr, nullptr, 0);
    split(Wv_s, bh, bl, nW);  gemm(ah, al, v, 0, 0, MM, HH, HH, nullptr, nullptr, 0);
    flash(q, k, v, ah, al, TT, /*causal=*/1);                    // ctx -> planes
    split(Wo_s, bh, bl, nW);  gemm(ah, al, x, 0, 0, MM, HH, HH, nullptr, input_, 0);

    // ---- cross attention ----
    layernorm_split_kernel<<<MM, 256>>>(x, g_mha, b_mha, ah, al);
    split(Wq_c, bh, bl, nW);  gemm(ah, al, q, 0, 0, MM, HH, HH, nullptr, nullptr, 0);
    split(enc, ah, al, nMH);                                     // enc -> planes
    split(Wk_c, bh, bl, nW);  gemm(ah, al, k, 0, 0, BB * TEE, HH, HH, nullptr, nullptr, 0);
    split(Wv_c, bh, bl, nW);  gemm(ah, al, v, 0, 0, BB * TEE, HH, HH, nullptr, nullptr, 0);
    flash(q, k, v, ah, al, TEE, /*causal=*/0);
    split(Wo_c, bh, bl, nW);  gemm(ah, al, z, 0, 0, MM, HH, HH, nullptr, x, 0);

    // ---- FFN ----
    layernorm_split_kernel<<<MM, 256>>>(z, g_ffn, b_ffn, ah, al);
    split(w1, bh, bl, nW1);   gemm(ah, al, 0, hh, hl, MM, FF, HH, b1, nullptr, 1);
    split(w2, bh, bl, nW1);   gemm(hh, hl, out, 0, 0, MM, HH, FF, b2, z, 0);
}

// round 8
// speedup vs baseline: 1.7786x; 1.0595x over previous
#include <cuda_runtime.h>
#include <cuda_bf16.h>
#include <math.h>
#include <stdint.h>

// Problem constants (fixed by the reference setup)
#define BB   8
#define TT   1024
#define TEE  1024
#define HH   1024
#define NHH  8
#define DKK  128
#define MM   (BB * TT)       // 8192 rows
#define FF   4096            // FFN hidden

// ---------------------------------------------------------------------------
// Scratch (static device globals)
// ---------------------------------------------------------------------------
__device__ float ws_q  [MM * HH];
__device__ float ws_k  [MM * HH];
__device__ float ws_v  [MM * HH];
__device__ float ws_x  [MM * HH];
__device__ float ws_z  [MM * HH];
// bf16 hi/lo operand planes
__device__ __nv_bfloat16 ws_ah [MM * HH];   // A-side planes (LN out / ctx / enc)
__device__ __nv_bfloat16 ws_al [MM * HH];
__device__ __nv_bfloat16 ws_hh [MM * FF];   // FFN hidden planes
__device__ __nv_bfloat16 ws_hl [MM * FF];
__device__ __nv_bfloat16 ws_bh [FF * HH];   // B-side (weight) planes
__device__ __nv_bfloat16 ws_bl [FF * HH];

// ---------------------------------------------------------------------------
// bf16 hi/lo split helpers
// ---------------------------------------------------------------------------
__device__ __forceinline__ void split_bf(float x, __nv_bfloat16& hi, __nv_bfloat16& lo) {
    hi = __float2bfloat16_rn(x);
    lo = __float2bfloat16_rn(x - __bfloat162float(hi));
}

// standalone split: 4 floats/thread; n % 1024 == 0
__global__ __launch_bounds__(256)
void split_kernel(const float* __restrict__ x,
                  __nv_bfloat16* __restrict__ hi, __nv_bfloat16* __restrict__ lo)
{
    const long long i = (long long)blockIdx.x * 256 + threadIdx.x;
    float4 v = ((const float4*)x)[i];
    __nv_bfloat16 h[4], l[4];
    split_bf(v.x, h[0], l[0]); split_bf(v.y, h[1], l[1]);
    split_bf(v.z, h[2], l[2]); split_bf(v.w, h[3], l[3]);
    __nv_bfloat162* hp = (__nv_bfloat162*)(hi + i * 4);
    __nv_bfloat162* lp = (__nv_bfloat162*)(lo + i * 4);
    hp[0] = __nv_bfloat162(h[0], h[1]); hp[1] = __nv_bfloat162(h[2], h[3]);
    lp[0] = __nv_bfloat162(l[0], l[1]); lp[1] = __nv_bfloat162(l[2], l[3]);
}

// ---------------------------------------------------------------------------
// bf16x3 tensor-core GEMM:  C = A[M,K] @ B[N,K]^T  (+ bias/relu/resid)
// A,B as hi/lo bf16 planes; 3 MMAs (AhBh+AhBl+AlBh) per m16n8k16.
// CTA tile 128x128, 8 warps (2x4), warp tile 64x32, K-chunk 32,
// cp.async double-buffered; fragments via ldmatrix.x4 (conflict-free with
// SROW=40: banks {0,20,8,28,16,4,24,12}x4 per 8-row phase).
// Output: fp32 C, or hi/lo planes (Chi/Clo non-null).
// Requires: M,N % 128 == 0, K % 32 == 0.
// ---------------------------------------------------------------------------
#define SROW 40                          // bf16 elems per smem row (32 data + 8 pad)
#define PLANE (128 * SROW)               // 5120 bf16 per plane
#define BUFSZ (4 * PLANE)                // Ah,Al,Bh,Bl
#define GEMM_SMEM (2 * BUFSZ * 2)        // 2 bufs, bytes = 81920

__device__ __forceinline__ void mma_bf16(float* c, const uint32_t* a, const uint32_t* b) {
    asm volatile(
        "mma.sync.aligned.m16n8k16.row.col.f32.bf16.bf16.f32 "
        "{%0,%1,%2,%3},{%4,%5,%6,%7},{%8,%9},{%0,%1,%2,%3};"
        : "+f"(c[0]), "+f"(c[1]), "+f"(c[2]), "+f"(c[3])
        : "r"(a[0]), "r"(a[1]), "r"(a[2]), "r"(a[3]), "r"(b[0]), "r"(b[1]));
}

__device__ __forceinline__ void ldm_x4(uint32_t addr, uint32_t* r) {
    asm volatile("ldmatrix.sync.aligned.m8n8.x4.shared.b16 {%0,%1,%2,%3}, [%4];"
        : "=r"(r[0]), "=r"(r[1]), "=r"(r[2]), "=r"(r[3]) : "r"(addr));
}

__device__ __forceinline__ void cp_async16(uint32_t smem_addr, const void* gptr) {
    asm volatile("cp.async.cg.shared.global [%0], [%1], 16;"
                 :: "r"(smem_addr), "l"(gptr));
}

__global__ __launch_bounds__(256, 2)
void gemm_bf16x3_kernel(const __nv_bfloat16* __restrict__ Ah,
                        const __nv_bfloat16* __restrict__ Al,
                        const __nv_bfloat16* __restrict__ Bh,
                        const __nv_bfloat16* __restrict__ Bl,
                        float* __restrict__ C,
                        __nv_bfloat16* __restrict__ Chi,
                        __nv_bfloat16* __restrict__ Clo,
                        int ldc, int M, int N, int K,
                        const float* __restrict__ bias,
                        const float* __restrict__ resid, int ldres,
                        int relu)
{
    extern __shared__ __nv_bfloat16 smb[];

    const int tid  = threadIdx.x;
    const int warp = tid >> 5;
    const int lane = tid & 31;
    const int wm = warp >> 2;              // 0..1
    const int wn = warp & 3;               // 0..3
    const int qr = lane >> 2;              // 0..7
    const int qc = lane & 3;               // 0..3
    const int m0 = blockIdx.y * 128;
    const int n0 = blockIdx.x * 128;

    const uint32_t sbase = (uint32_t)__cvta_generic_to_shared(smb);

    // ldmatrix per-lane addressing
    const int aRow = lane & 15;            // rows 0-15 of the 16x16 A tile
    const int aKof = (lane >> 4) * 8;      // k offset 0/8
    const int bRow = (lane >> 4) * 8 + (lane & 7);  // 0..15 within nt-pair
    const int bKof = ((lane >> 3) & 1) * 8;         // k offset 0/8

    float acc[4][4][4];
    #pragma unroll
    for (int mt = 0; mt < 4; ++mt)
        #pragma unroll
        for (int nt = 0; nt < 4; ++nt)
            #pragma unroll
            for (int r = 0; r < 4; ++r) acc[mt][nt][r] = 0.f;

    // copy: per op-plane 128 rows x 4 granules (16B = 8 bf16); 2048 total, 8/thread
    auto issue = [&](int buf, int kk0) {
        #pragma unroll
        for (int i = 0; i < 8; ++i) {
            const int op   = i >> 1;
            const int widx = (i & 1) * 256 + tid;
            const int row  = widx >> 2;
            const int g    = widx & 3;
            const __nv_bfloat16* src;
            if      (op == 0) src = Ah + (long long)(m0 + row) * K + kk0 + g * 8;
            else if (op == 1) src = Al + (long long)(m0 + row) * K + kk0 + g * 8;
            else if (op == 2) src = Bh + (long long)(n0 + row) * K + kk0 + g * 8;
            else              src = Bl + (long long)(n0 + row) * K + kk0 + g * 8;
            const uint32_t soff = (uint32_t)((buf * BUFSZ + op * PLANE + row * SROW + g * 8) * 2);
            cp_async16(sbase + soff, src);
        }
        asm volatile("cp.async.commit_group;");
    };

    const int nchunks = K >> 5;            // K / 32

    issue(0, 0);
    asm volatile("cp.async.wait_group 0;");
    __syncthreads();

    for (int t = 0; t < nchunks; ++t) {
        const int buf = t & 1;
        if (t + 1 < nchunks) issue(buf ^ 1, (t + 1) * 32);

        const uint32_t bufB = (uint32_t)(buf * BUFSZ);   // element offset

        #pragma unroll
        for (int ks = 0; ks < 2; ++ks) {
            const int k0 = ks * 16;
            // B fragments: pair p covers nt=2p, 2p+1 (hi & lo planes)
            uint32_t bhf[2][4], blf[2][4];
            #pragma unroll
            for (int p = 0; p < 2; ++p) {
                const uint32_t off = sbase +
                    (uint32_t)((bufB + 2 * PLANE + (wn * 32 + p * 16 + bRow) * SROW + k0 + bKof) * 2);
                ldm_x4(off, bhf[p]);
                ldm_x4(off + 2 * PLANE, blf[p]);   // +PLANE elems = +2*PLANE bytes
            }
            #pragma unroll
            for (int mt = 0; mt < 4; ++mt) {
                uint32_t ahf[4], alf[4];
                const uint32_t off = sbase +
                    (uint32_t)((bufB + (wm * 64 + mt * 16 + aRow) * SROW + k0 + aKof) * 2);
                ldm_x4(off, ahf);
                ldm_x4(off + 2 * PLANE, alf);
                #pragma unroll
                for (int nt = 0; nt < 4; ++nt) {
                    const uint32_t* b2h = &bhf[nt >> 1][(nt & 1) * 2];
                    const uint32_t* b2l = &blf[nt >> 1][(nt & 1) * 2];
                    mma_bf16(acc[mt][nt], ahf, b2h);   // Ah*Bh
                    mma_bf16(acc[mt][nt], ahf, b2l);   // Ah*Bl
                    mma_bf16(acc[mt][nt], alf, b2h);   // Al*Bh
                }
            }
        }

        if (t + 1 < nchunks) {
            asm volatile("cp.async.wait_group 0;");
            __syncthreads();
        }
    }

    // Epilogue: frag -> rows qr,+8 ; cols 2*qc,+1.
    #pragma unroll
    for (int mt = 0; mt < 4; ++mt) {
        const int row0 = m0 + wm * 64 + mt * 16 + qr;
        #pragma unroll
        for (int nt = 0; nt < 4; ++nt) {
            const int col = n0 + wn * 32 + nt * 8 + qc * 2;
            float2 v0 = make_float2(acc[mt][nt][0], acc[mt][nt][1]);
            float2 v1 = make_float2(acc[mt][nt][2], acc[mt][nt][3]);
            if (bias) {
                float2 b2 = *(const float2*)(bias + col);
                v0.x += b2.x; v0.y += b2.y;
                v1.x += b2.x; v1.y += b2.y;
            }
            if (relu) {
                v0.x = fmaxf(v0.x, 0.f); v0.y = fmaxf(v0.y, 0.f);
                v1.x = fmaxf(v1.x, 0.f); v1.y = fmaxf(v1.y, 0.f);
            }
            if (resid) {
                float2 r0 = *(const float2*)(resid + (long long)row0 * ldres + col);
                float2 r1 = *(const float2*)(resid + (long long)(row0 + 8) * ldres + col);
                v0.x += r0.x; v0.y += r0.y;
                v1.x += r1.x; v1.y += r1.y;
            }
            if (Chi) {
                __nv_bfloat16 h0a,l0a,h0b,l0b,h1a,l1a,h1b,l1b;
                split_bf(v0.x, h0a, l0a); split_bf(v0.y, h0b, l0b);
                split_bf(v1.x, h1a, l1a); split_bf(v1.y, h1b, l1b);
                *(__nv_bfloat162*)(Chi + (long long)row0 * ldc + col)       = __nv_bfloat162(h0a, h0b);
                *(__nv_bfloat162*)(Clo + (long long)row0 * ldc + col)       = __nv_bfloat162(l0a, l0b);
                *(__nv_bfloat162*)(Chi + (long long)(row0 + 8) * ldc + col) = __nv_bfloat162(h1a, h1b);
                *(__nv_bfloat162*)(Clo + (long long)(row0 + 8) * ldc + col) = __nv_bfloat162(l1a, l1b);
            } else {
                *(float2*)(C + (long long)row0 * ldc + col)       = v0;
                *(float2*)(C + (long long)(row0 + 8) * ldc + col) = v1;
            }
        }
    }
}

// ---------------------------------------------------------------------------
// Flash attention (fp32, DK=128). Epilogue writes bf16 hi/lo planes.
// ---------------------------------------------------------------------------
#define BQ 64
#define BK 32
#define SPAD 132
#define FLASH_SMEM ((BQ*SPAD + 2*BK*SPAD + BQ*BK) * 4)

__global__ __launch_bounds__(256)
void flash_attn_kernel(const float* __restrict__ Qg, const float* __restrict__ Kg,
                       const float* __restrict__ Vg,
                       __nv_bfloat16* __restrict__ Ohi, __nv_bfloat16* __restrict__ Olo,
                       int Tk, int causal)
{
    extern __shared__ float sm[];
    float* sQ = sm;
    float* sK = sQ + BQ * SPAD;
    float* sV = sK + BK * SPAD;
    float* sP = sV + BK * SPAD;

    const int tid = threadIdx.x;
    const int tx = tid & 15, ty = tid >> 4;
    const int q0 = blockIdx.x * BQ;
    const int bh = blockIdx.y;
    const int bb = bh >> 3, hh = bh & 7;

    const float* Qp = Qg + ((long long)(bb * TT + q0)) * HH + hh * DKK;
    const float* Kp = Kg + ((long long)bb * Tk) * HH + hh * DKK;
    const float* Vp = Vg + ((long long)bb * Tk) * HH + hh * DKK;

    #pragma unroll
    for (int i = 0; i < 8; ++i) {
        int f = i * 256 + tid;
        int row = f >> 5, c4 = (f & 31) * 4;
        *(float4*)&sQ[row * SPAD + c4] = *(const float4*)(Qp + (long long)row * HH + c4);
    }

    const float scale = 0.08838834764831845f;
    float m[4], l[4], o[4][8];
    #pragma unroll
    for (int i = 0; i < 4; ++i) {
        m[i] = -INFINITY; l[i] = 0.f;
        #pragma unroll
        for (int c = 0; c < 8; ++c) o[i][c] = 0.f;
    }

    const int nkt = causal ? (q0 / BK + 2) : (Tk / BK);

    for (int kt = 0; kt < nkt; ++kt) {
        __syncthreads();
        const long long krow0 = (long long)kt * BK;
        #pragma unroll
        for (int i = 0; i < 4; ++i) {
            int f = i * 256 + tid;
            int row = f >> 5, c4 = (f & 31) * 4;
            *(float4*)&sK[row * SPAD + c4] = *(const float4*)(Kp + (krow0 + row) * HH + c4);
            *(float4*)&sV[row * SPAD + c4] = *(const float4*)(Vp + (krow0 + row) * HH + c4);
        }
        __syncthreads();

        float s[4][2];
        #pragma unroll
        for (int i = 0; i < 4; ++i) { s[i][0] = 0.f; s[i][1] = 0.f; }
        #pragma unroll 4
        for (int d = 0; d < DKK; d += 4) {
            float4 kv0 = *(const float4*)&sK[(tx     ) * SPAD + d];
            float4 kv1 = *(const float4*)&sK[(tx + 16) * SPAD + d];
            #pragma unroll
            for (int i = 0; i < 4; ++i) {
                float4 qv = *(const float4*)&sQ[(ty * 4 + i) * SPAD + d];
                s[i][0] += qv.x * kv0.x + qv.y * kv0.y + qv.z * kv0.z + qv.w * kv0.w;
                s[i][1] += qv.x * kv1.x + qv.y * kv1.y + qv.z * kv1.z + qv.w * kv1.w;
            }
        }

        #pragma unroll
        for (int i = 0; i < 4; ++i) {
            int qg = q0 + ty * 4 + i;
            #pragma unroll
            for (int j = 0; j < 2; ++j) {
                s[i][j] *= scale;
                if (causal && (kt * BK + tx + j * 16 > qg)) s[i][j] = -INFINITY;
            }
        }

        float corr[4];
        #pragma unroll
        for (int i = 0; i < 4; ++i) {
            float mx = fmaxf(s[i][0], s[i][1]);
            #pragma unroll
            for (int off = 8; off; off >>= 1)
                mx = fmaxf(mx, __shfl_xor_sync(0xffffffffu, mx, off));
            float mn = fmaxf(m[i], mx);
            corr[i] = __expf(m[i] - mn);
            float p0 = __expf(s[i][0] - mn);
            float p1 = __expf(s[i][1] - mn);
            float ts = p0 + p1;
            #pragma unroll
            for (int off = 8; off; off >>= 1)
                ts += __shfl_xor_sync(0xffffffffu, ts, off);
            l[i] = l[i] * corr[i] + ts;
            m[i] = mn;
            sP[(ty * 4 + i) * BK + tx     ] = p0;
            sP[(ty * 4 + i) * BK + tx + 16] = p1;
            #pragma unroll
            for (int c = 0; c < 8; ++c) o[i][c] *= corr[i];
        }
        __syncthreads();

        #pragma unroll
        for (int k4 = 0; k4 < BK; k4 += 4) {
            float4 pv[4];
            #pragma unroll
            for (int i = 0; i < 4; ++i)
                pv[i] = *(const float4*)&sP[(ty * 4 + i) * BK + k4];
            #pragma unroll
            for (int kk = 0; kk < 4; ++kk) {
                float4 v0 = *(const float4*)&sV[(k4 + kk) * SPAD + tx * 8];
                float4 v1 = *(const float4*)&sV[(k4 + kk) * SPAD + tx * 8 + 4];
                #pragma unroll
                for (int i = 0; i < 4; ++i) {
                    float p = (kk == 0) ? pv[i].x : (kk == 1) ? pv[i].y
                            : (kk == 2) ? pv[i].z : pv[i].w;
                    o[i][0] += p * v0.x; o[i][1] += p * v0.y;
                    o[i][2] += p * v0.z; o[i][3] += p * v0.w;
                    o[i][4] += p * v1.x; o[i][5] += p * v1.y;
                    o[i][6] += p * v1.z; o[i][7] += p * v1.w;
                }
            }
        }
    }

    #pragma unroll
    for (int i = 0; i < 4; ++i) {
        float inv = 1.f / l[i];
        __nv_bfloat16 h[8], lo[8];
        #pragma unroll
        for (int c = 0; c < 8; ++c) split_bf(o[i][c] * inv, h[c], lo[c]);
        long long off = ((long long)(bb * TT + q0 + ty * 4 + i)) * HH + hh * DKK + tx * 8;
        __nv_bfloat162* hp = (__nv_bfloat162*)(Ohi + off);
        __nv_bfloat162* lp = (__nv_bfloat162*)(Olo + off);
        hp[0] = __nv_bfloat162(h[0], h[1]);  hp[1] = __nv_bfloat162(h[2], h[3]);
        hp[2] = __nv_bfloat162(h[4], h[5]);  hp[3] = __nv_bfloat162(h[6], h[7]);
        lp[0] = __nv_bfloat162(lo[0], lo[1]); lp[1] = __nv_bfloat162(lo[2], lo[3]);
        lp[2] = __nv_bfloat162(lo[4], lo[5]); lp[3] = __nv_bfloat162(lo[6], lo[7]);
    }
}

// ---------------------------------------------------------------------------
// LayerNorm over last dim (1024); writes bf16 hi/lo planes directly.
// ---------------------------------------------------------------------------
__global__ __launch_bounds__(256)
void layernorm_split_kernel(const float* __restrict__ x, const float* __restrict__ g,
                            const float* __restrict__ b,
                            __nv_bfloat16* __restrict__ yhi,
                            __nv_bfloat16* __restrict__ ylo)
{
    const long long row = blockIdx.x;
    const int tid = threadIdx.x;
    float4 v = ((const float4*)(x + row * HH))[tid];

    __shared__ float red[8];
    float s = v.x + v.y + v.z + v.w;
    #pragma unroll
    for (int o = 16; o; o >>= 1) s += __shfl_xor_sync(0xffffffffu, s, o);
    if ((tid & 31) == 0) red[tid >> 5] = s;
    __syncthreads();
    float mean = (red[0] + red[1] + red[2] + red[3] +
                  red[4] + red[5] + red[6] + red[7]) * (1.f / HH);
    __syncthreads();

    float dx = v.x - mean, dy = v.y - mean, dz = v.z - mean, dw = v.w - mean;
    float sq = dx * dx + dy * dy + dz * dz + dw * dw;
    #pragma unroll
    for (int o = 16; o; o >>= 1) sq += __shfl_xor_sync(0xffffffffu, sq, o);
    if ((tid & 31) == 0) red[tid >> 5] = sq;
    __syncthreads();
    float var = (red[0] + red[1] + red[2] + red[3] +
                 red[4] + red[5] + red[6] + red[7]) * (1.f / HH);
    float rstd = rsqrtf(var + 1e-5f);

    float4 g4 = ((const float4*)g)[tid];
    float4 b4 = ((const float4*)b)[tid];
    float y0 = dx * rstd * g4.x + b4.x;
    float y1 = dy * rstd * g4.y + b4.y;
    float y2 = dz * rstd * g4.z + b4.z;
    float y3 = dw * rstd * g4.w + b4.w;

    __nv_bfloat16 h0,l0,h1,l1,h2,l2,h3,l3;
    split_bf(y0, h0, l0); split_bf(y1, h1, l1);
    split_bf(y2, h2, l2); split_bf(y3, h3, l3);
    __nv_bfloat162* hp = (__nv_bfloat162*)(yhi + row * HH + tid * 4);
    __nv_bfloat162* lp = (__nv_bfloat162*)(ylo + row * HH + tid * 4);
    hp[0] = __nv_bfloat162(h0, h1); hp[1] = __nv_bfloat162(h2, h3);
    lp[0] = __nv_bfloat162(l0, l1); lp[1] = __nv_bfloat162(l2, l3);
}

// ---------------------------------------------------------------------------
// Host orchestration
// ---------------------------------------------------------------------------
extern "C" void kernel_launch(void* const* d_in, const int* in_sizes, int n_in,
                              void* d_out, int out_size)
{
    const float* input_ = (const float*)d_in[0];
    const float* enc    = (const float*)d_in[1];
    const float* Wq_s = (const float*)d_in[4];
    const float* Wk_s = (const float*)d_in[5];
    const float* Wv_s = (const float*)d_in[6];
    const float* Wo_s = (const float*)d_in[7];
    const float* Wq_c = (const float*)d_in[8];
    const float* Wk_c = (const float*)d_in[9];
    const float* Wv_c = (const float*)d_in[10];
    const float* Wo_c = (const float*)d_in[11];
    const float* w1   = (const float*)d_in[12];
    const float* b1   = (const float*)d_in[13];
    const float* w2   = (const float*)d_in[14];
    const float* b2   = (const float*)d_in[15];
    const float* g_mmha = (const float*)d_in[16];
    const float* b_mmha = (const float*)d_in[17];
    const float* g_mha  = (const float*)d_in[18];
    const float* b_mha  = (const float*)d_in[19];
    const float* g_ffn  = (const float*)d_in[20];
    const float* b_ffn  = (const float*)d_in[21];
    float* out = (float*)d_out;

    float *q, *k, *v, *x, *z;
    __nv_bfloat16 *ah, *al, *hh, *hl, *bh, *bl;
    cudaGetSymbolAddress((void**)&q,  ws_q);
    cudaGetSymbolAddress((void**)&k,  ws_k);
    cudaGetSymbolAddress((void**)&v,  ws_v);
    cudaGetSymbolAddress((void**)&x,  ws_x);
    cudaGetSymbolAddress((void**)&z,  ws_z);
    cudaGetSymbolAddress((void**)&ah, ws_ah);
    cudaGetSymbolAddress((void**)&al, ws_al);
    cudaGetSymbolAddress((void**)&hh, ws_hh);
    cudaGetSymbolAddress((void**)&hl, ws_hl);
    cudaGetSymbolAddress((void**)&bh, ws_bh);
    cudaGetSymbolAddress((void**)&bl, ws_bl);

    cudaFuncSetAttribute(flash_attn_kernel,
                         cudaFuncAttributeMaxDynamicSharedMemorySize, FLASH_SMEM);
    cudaFuncSetAttribute(gemm_bf16x3_kernel,
                         cudaFuncAttributeMaxDynamicSharedMemorySize, GEMM_SMEM);

    auto split = [&](const float* src, __nv_bfloat16* h, __nv_bfloat16* l, long long n) {
        split_kernel<<<(int)(n / 1024), 256>>>(src, h, l);
    };
    auto gemm = [&](const __nv_bfloat16* pah, const __nv_bfloat16* pal,
                    float* C, __nv_bfloat16* chi, __nv_bfloat16* clo,
                    int M, int N, int K,
                    const float* bias, const float* resid, int relu) {
        dim3 grid(N / 128, M / 128, 1);
        gemm_bf16x3_kernel<<<grid, 256, GEMM_SMEM>>>(pah, pal, bh, bl,
                                                     C, chi, clo, N, M, N, K,
                                                     bias, resid, N, relu);
    };
    auto flash = [&](const float* Q, const float* K, const float* V,
                     __nv_bfloat16* ohi, __nv_bfloat16* olo, int Tk, int causal) {
        dim3 grid(TT / BQ, BB * NHH);
        flash_attn_kernel<<<grid, 256, FLASH_SMEM>>>(Q, K, V, ohi, olo, Tk, causal);
    };

    const long long nW  = (long long)HH * HH;   // 1M elems
    const long long nW1 = (long long)FF * HH;   // 4M elems
    const long long nMH = (long long)MM * HH;   // 8M elems

    // ---- self attention ----
    layernorm_split_kernel<<<MM, 256>>>(input_, g_mmha, b_mmha, ah, al);
    split(Wq_s, bh, bl, nW);  gemm(ah, al, q, 0, 0, MM, HH, HH, nullptr, nullptr, 0);
    split(Wk_s, bh, bl, nW);  gemm(ah, al, k, 0, 0, MM, HH, HH, nullptr, nullptr, 0);
    split(Wv_s, bh, bl, nW);  gemm(ah, al, v, 0, 0, MM, HH, HH, nullptr, nullptr, 0);
    flash(q, k, v, ah, al, TT, /*causal=*/1);                    // ctx -> planes
    split(Wo_s, bh, bl, nW);  gemm(ah, al, x, 0, 0, MM, HH, HH, nullptr, input_, 0);

    // ---- cross attention ----
    layernorm_split_kernel<<<MM, 256>>>(x, g_mha, b_mha, ah, al);
    split(Wq_c, bh, bl, nW);  gemm(ah, al, q, 0, 0, MM, HH, HH, nullptr, nullptr, 0);
    split(enc, ah, al, nMH);                                     // enc -> planes
    split(Wk_c, bh, bl, nW);  gemm(ah, al, k, 0, 0, BB * TEE, HH, HH, nullptr, nullptr, 0);
    split(Wv_c, bh, bl, nW);  gemm(ah, al, v, 0, 0, BB * TEE, HH, HH, nullptr, nullptr, 0);
    flash(q, k, v, ah, al, TEE, /*causal=*/0);
    split(Wo_c, bh, bl, nW);  gemm(ah, al, z, 0, 0, MM, HH, HH, nullptr, x, 0);

    // ---- FFN ----
    layernorm_split_kernel<<<MM, 256>>>(z, g_ffn, b_ffn, ah, al);
    split(w1, bh, bl, nW1);   gemm(ah, al, 0, hh, hl, MM, FF, HH, b1, nullptr, 1);
    split(w2, bh, bl, nW1);   gemm(hh, hl, out, 0, 0, MM, HH, FF, b2, z, 0);
}

// round 10
// speedup vs baseline: 2.1347x; 1.2002x over previous
#include <cuda_runtime.h>
#include <cuda_bf16.h>
#include <math.h>
#include <stdint.h>

// Problem constants (fixed by the reference setup)
#define BB   8
#define TT   1024
#define TEE  1024
#define HH   1024
#define NHH  8
#define DKK  128
#define MM   (BB * TT)       // 8192 rows
#define FF   4096            // FFN hidden

// ---------------------------------------------------------------------------
// Scratch (static device globals)
// ---------------------------------------------------------------------------
__device__ float ws_q  [MM * HH];
__device__ float ws_k  [MM * HH];
__device__ float ws_v  [MM * HH];
__device__ float ws_x  [MM * HH];
__device__ float ws_z  [MM * HH];
__device__ float ws_a  [MM * HH];    // tf32-rounded A operand (LN out / ctx / enc)
__device__ float ws_hid[MM * FF];    // tf32-rounded FFN hidden
__device__ float ws_b  [FF * HH];    // tf32-rounded weight operand

// ---------------------------------------------------------------------------
// tf32 rna rounding helper (value stays fp32-representable, low 13 bits zero)
// ---------------------------------------------------------------------------
__device__ __forceinline__ float rna_tf32(float x) {
    uint32_t u;
    asm("cvt.rna.tf32.f32 %0, %1;" : "=r"(u) : "f"(x));
    return __uint_as_float(u);
}

// standalone round: 4 floats/thread; n % 1024 == 0
__global__ __launch_bounds__(256)
void round_kernel(const float* __restrict__ x, float* __restrict__ y)
{
    const long long i = (long long)blockIdx.x * 256 + threadIdx.x;
    float4 v = ((const float4*)x)[i];
    v.x = rna_tf32(v.x); v.y = rna_tf32(v.y);
    v.z = rna_tf32(v.z); v.w = rna_tf32(v.w);
    ((float4*)y)[i] = v;
}

// ---------------------------------------------------------------------------
// tf32 tensor-core GEMM:  C = A[M,K] @ B[N,K]^T  (+ bias/relu/resid)
// Operands are fp32 arrays pre-rounded to tf32 (rna) by producers.
// CTA tile 128x128, 8 warps (2x4), warp tile 64x32, K-chunk 32,
// cp.async double-buffered; fragments via ldmatrix.x4 on 32-bit data
// (SROWF=36 floats -> each 8-row phase covers all 32 banks, conflict-free).
// round_out: write tf32-rounded C (operand for next GEMM).
// Requires: M,N % 128 == 0, K % 32 == 0.
// ---------------------------------------------------------------------------
#define SROWF 36
#define PLANEF (128 * SROWF)             // 4608 floats
#define BUFF (2 * PLANEF)                // A plane + B plane
#define GEMM_SMEM (2 * BUFF * 4)         // 73728 B

__device__ __forceinline__ void mma_tf32(float* c, const uint32_t* a, const uint32_t* b) {
    asm volatile(
        "mma.sync.aligned.m16n8k8.row.col.f32.tf32.tf32.f32 "
        "{%0,%1,%2,%3},{%4,%5,%6,%7},{%8,%9},{%0,%1,%2,%3};"
        : "+f"(c[0]), "+f"(c[1]), "+f"(c[2]), "+f"(c[3])
        : "r"(a[0]), "r"(a[1]), "r"(a[2]), "r"(a[3]), "r"(b[0]), "r"(b[1]));
}

__device__ __forceinline__ void ldm_x4(uint32_t addr, uint32_t* r) {
    asm volatile("ldmatrix.sync.aligned.m8n8.x4.shared.b16 {%0,%1,%2,%3}, [%4];"
        : "=r"(r[0]), "=r"(r[1]), "=r"(r[2]), "=r"(r[3]) : "r"(addr));
}

__device__ __forceinline__ void cp_async16(uint32_t smem_addr, const void* gptr) {
    asm volatile("cp.async.cg.shared.global [%0], [%1], 16;"
                 :: "r"(smem_addr), "l"(gptr));
}

__global__ __launch_bounds__(256, 2)
void gemm_tf32_kernel(const float* __restrict__ A,
                      const float* __restrict__ B,
                      float* __restrict__ C,
                      int ldc, int M, int N, int K,
                      const float* __restrict__ bias,
                      const float* __restrict__ resid, int ldres,
                      int relu, int round_out)
{
    extern __shared__ float smf[];

    const int tid  = threadIdx.x;
    const int warp = tid >> 5;
    const int lane = tid & 31;
    const int wm = warp >> 2;
    const int wn = warp & 3;
    const int qr = lane >> 2;
    const int qc = lane & 3;
    const int m0 = blockIdx.y * 128;
    const int n0 = blockIdx.x * 128;

    const uint32_t sbase = (uint32_t)__cvta_generic_to_shared(smf);

    // ldmatrix per-lane addressing (32-bit element matrices)
    // A (m16 x k8): m0=(r0-7,k0-3) m1=(r8-15,k0-3) m2=(r0-7,k4-7) m3=(r8-15,k4-7)
    const int aRow = ((lane >> 3) & 1) * 8 + (lane & 7);
    const int aKof = (lane >> 4) * 4;
    // B pair (16 n-rows x k8): m0=(n0-7,k0-3) m1=(n0-7,k4-7) m2=(n8-15,k0-3) m3=(n8-15,k4-7)
    const int bRow = (lane >> 4) * 8 + (lane & 7);
    const int bKof = ((lane >> 3) & 1) * 4;

    float acc[4][4][4];
    #pragma unroll
    for (int mt = 0; mt < 4; ++mt)
        #pragma unroll
        for (int nt = 0; nt < 4; ++nt)
            #pragma unroll
            for (int r = 0; r < 4; ++r) acc[mt][nt][r] = 0.f;

    // copy: per plane 128 rows x 8 granules (16B = 4 floats); 2048 total, 8/thread
    auto issue = [&](int buf, int kk0) {
        #pragma unroll
        for (int i = 0; i < 8; ++i) {
            const int op   = i >> 2;                 // 0=A, 1=B
            const int widx = (i & 3) * 256 + tid;    // 0..1023
            const int row  = widx >> 3;
            const int g    = widx & 7;
            const float* src = op
                ? B + (long long)(n0 + row) * K + kk0 + g * 4
                : A + (long long)(m0 + row) * K + kk0 + g * 4;
            const uint32_t soff = (uint32_t)((buf * BUFF + op * PLANEF + row * SROWF + g * 4) * 4);
            cp_async16(sbase + soff, src);
        }
        asm volatile("cp.async.commit_group;");
    };

    const int nchunks = K >> 5;

    issue(0, 0);
    asm volatile("cp.async.wait_group 0;");
    __syncthreads();

    for (int t = 0; t < nchunks; ++t) {
        const int buf = t & 1;
        if (t + 1 < nchunks) issue(buf ^ 1, (t + 1) * 32);

        const uint32_t bufF = (uint32_t)(buf * BUFF);

        #pragma unroll
        for (int ks = 0; ks < 4; ++ks) {
            const int k0 = ks * 8;
            uint32_t bf[2][4];
            #pragma unroll
            for (int p = 0; p < 2; ++p) {
                const uint32_t off = sbase +
                    (uint32_t)((bufF + PLANEF + (wn * 32 + p * 16 + bRow) * SROWF + k0 + bKof) * 4);
                ldm_x4(off, bf[p]);
            }
            #pragma unroll
            for (int mt = 0; mt < 4; ++mt) {
                uint32_t af[4];
                const uint32_t off = sbase +
                    (uint32_t)((bufF + (wm * 64 + mt * 16 + aRow) * SROWF + k0 + aKof) * 4);
                ldm_x4(off, af);
                #pragma unroll
                for (int nt = 0; nt < 4; ++nt) {
                    const uint32_t* bb = &bf[nt >> 1][(nt & 1) * 2];
                    mma_tf32(acc[mt][nt], af, bb);
                }
            }
        }

        if (t + 1 < nchunks) {
            asm volatile("cp.async.wait_group 0;");
            __syncthreads();
        }
    }

    // Epilogue: frag -> rows qr,+8 ; cols 2*qc,+1.
    #pragma unroll
    for (int mt = 0; mt < 4; ++mt) {
        const int row0 = m0 + wm * 64 + mt * 16 + qr;
        #pragma unroll
        for (int nt = 0; nt < 4; ++nt) {
            const int col = n0 + wn * 32 + nt * 8 + qc * 2;
            float2 v0 = make_float2(acc[mt][nt][0], acc[mt][nt][1]);
            float2 v1 = make_float2(acc[mt][nt][2], acc[mt][nt][3]);
            if (bias) {
                float2 b2 = *(const float2*)(bias + col);
                v0.x += b2.x; v0.y += b2.y;
                v1.x += b2.x; v1.y += b2.y;
            }
            if (relu) {
                v0.x = fmaxf(v0.x, 0.f); v0.y = fmaxf(v0.y, 0.f);
                v1.x = fmaxf(v1.x, 0.f); v1.y = fmaxf(v1.y, 0.f);
            }
            if (resid) {
                float2 r0 = *(const float2*)(resid + (long long)row0 * ldres + col);
                float2 r1 = *(const float2*)(resid + (long long)(row0 + 8) * ldres + col);
                v0.x += r0.x; v0.y += r0.y;
                v1.x += r1.x; v1.y += r1.y;
            }
            if (round_out) {
                v0.x = rna_tf32(v0.x); v0.y = rna_tf32(v0.y);
                v1.x = rna_tf32(v1.x); v1.y = rna_tf32(v1.y);
            }
            *(float2*)(C + (long long)row0 * ldc + col)       = v0;
            *(float2*)(C + (long long)(row0 + 8) * ldc + col) = v1;
        }
    }
}

// ---------------------------------------------------------------------------
// Flash attention (fp32, DK=128). Epilogue writes tf32-rounded fp32 ctx.
// ---------------------------------------------------------------------------
#define BQ 64
#define BK 32
#define SPAD 132
#define FLASH_SMEM ((BQ*SPAD + 2*BK*SPAD + BQ*BK) * 4)

__global__ __launch_bounds__(256)
void flash_attn_kernel(const float* __restrict__ Qg, const float* __restrict__ Kg,
                       const float* __restrict__ Vg, float* __restrict__ Og,
                       int Tk, int causal)
{
    extern __shared__ float sm[];
    float* sQ = sm;
    float* sK = sQ + BQ * SPAD;
    float* sV = sK + BK * SPAD;
    float* sP = sV + BK * SPAD;

    const int tid = threadIdx.x;
    const int tx = tid & 15, ty = tid >> 4;
    const int q0 = blockIdx.x * BQ;
    const int bh = blockIdx.y;
    const int bb = bh >> 3, hh = bh & 7;

    const float* Qp = Qg + ((long long)(bb * TT + q0)) * HH + hh * DKK;
    const float* Kp = Kg + ((long long)bb * Tk) * HH + hh * DKK;
    const float* Vp = Vg + ((long long)bb * Tk) * HH + hh * DKK;

    #pragma unroll
    for (int i = 0; i < 8; ++i) {
        int f = i * 256 + tid;
        int row = f >> 5, c4 = (f & 31) * 4;
        *(float4*)&sQ[row * SPAD + c4] = *(const float4*)(Qp + (long long)row * HH + c4);
    }

    const float scale = 0.08838834764831845f;
    float m[4], l[4], o[4][8];
    #pragma unroll
    for (int i = 0; i < 4; ++i) {
        m[i] = -INFINITY; l[i] = 0.f;
        #pragma unroll
        for (int c = 0; c < 8; ++c) o[i][c] = 0.f;
    }

    const int nkt = causal ? (q0 / BK + 2) : (Tk / BK);

    for (int kt = 0; kt < nkt; ++kt) {
        __syncthreads();
        const long long krow0 = (long long)kt * BK;
        #pragma unroll
        for (int i = 0; i < 4; ++i) {
            int f = i * 256 + tid;
            int row = f >> 5, c4 = (f & 31) * 4;
            *(float4*)&sK[row * SPAD + c4] = *(const float4*)(Kp + (krow0 + row) * HH + c4);
            *(float4*)&sV[row * SPAD + c4] = *(const float4*)(Vp + (krow0 + row) * HH + c4);
        }
        __syncthreads();

        float s[4][2];
        #pragma unroll
        for (int i = 0; i < 4; ++i) { s[i][0] = 0.f; s[i][1] = 0.f; }
        #pragma unroll 4
        for (int d = 0; d < DKK; d += 4) {
            float4 kv0 = *(const float4*)&sK[(tx     ) * SPAD + d];
            float4 kv1 = *(const float4*)&sK[(tx + 16) * SPAD + d];
            #pragma unroll
            for (int i = 0; i < 4; ++i) {
                float4 qv = *(const float4*)&sQ[(ty * 4 + i) * SPAD + d];
                s[i][0] += qv.x * kv0.x + qv.y * kv0.y + qv.z * kv0.z + qv.w * kv0.w;
                s[i][1] += qv.x * kv1.x + qv.y * kv1.y + qv.z * kv1.z + qv.w * kv1.w;
            }
        }

        #pragma unroll
        for (int i = 0; i < 4; ++i) {
            int qg = q0 + ty * 4 + i;
            #pragma unroll
            for (int j = 0; j < 2; ++j) {
                s[i][j] *= scale;
                if (causal && (kt * BK + tx + j * 16 > qg)) s[i][j] = -INFINITY;
            }
        }

        float corr[4];
        #pragma unroll
        for (int i = 0; i < 4; ++i) {
            float mx = fmaxf(s[i][0], s[i][1]);
            #pragma unroll
            for (int off = 8; off; off >>= 1)
                mx = fmaxf(mx, __shfl_xor_sync(0xffffffffu, mx, off));
            float mn = fmaxf(m[i], mx);
            corr[i] = __expf(m[i] - mn);
            float p0 = __expf(s[i][0] - mn);
            float p1 = __expf(s[i][1] - mn);
            float ts = p0 + p1;
            #pragma unroll
            for (int off = 8; off; off >>= 1)
                ts += __shfl_xor_sync(0xffffffffu, ts, off);
            l[i] = l[i] * corr[i] + ts;
            m[i] = mn;
            sP[(ty * 4 + i) * BK + tx     ] = p0;
            sP[(ty * 4 + i) * BK + tx + 16] = p1;
            #pragma unroll
            for (int c = 0; c < 8; ++c) o[i][c] *= corr[i];
        }
        __syncthreads();

        #pragma unroll
        for (int k4 = 0; k4 < BK; k4 += 4) {
            float4 pv[4];
            #pragma unroll
            for (int i = 0; i < 4; ++i)
                pv[i] = *(const float4*)&sP[(ty * 4 + i) * BK + k4];
            #pragma unroll
            for (int kk = 0; kk < 4; ++kk) {
                float4 v0 = *(const float4*)&sV[(k4 + kk) * SPAD + tx * 8];
                float4 v1 = *(const float4*)&sV[(k4 + kk) * SPAD + tx * 8 + 4];
                #pragma unroll
                for (int i = 0; i < 4; ++i) {
                    float p = (kk == 0) ? pv[i].x : (kk == 1) ? pv[i].y
                            : (kk == 2) ? pv[i].z : pv[i].w;
                    o[i][0] += p * v0.x; o[i][1] += p * v0.y;
                    o[i][2] += p * v0.z; o[i][3] += p * v0.w;
                    o[i][4] += p * v1.x; o[i][5] += p * v1.y;
                    o[i][6] += p * v1.z; o[i][7] += p * v1.w;
                }
            }
        }
    }

    #pragma unroll
    for (int i = 0; i < 4; ++i) {
        float inv = 1.f / l[i];
        float4 r0, r1;
        r0.x = rna_tf32(o[i][0] * inv); r0.y = rna_tf32(o[i][1] * inv);
        r0.z = rna_tf32(o[i][2] * inv); r0.w = rna_tf32(o[i][3] * inv);
        r1.x = rna_tf32(o[i][4] * inv); r1.y = rna_tf32(o[i][5] * inv);
        r1.z = rna_tf32(o[i][6] * inv); r1.w = rna_tf32(o[i][7] * inv);
        float* op = Og + ((long long)(bb * TT + q0 + ty * 4 + i)) * HH + hh * DKK + tx * 8;
        *(float4*)op = r0;
        *(float4*)(op + 4) = r1;
    }
}

// ---------------------------------------------------------------------------
// LayerNorm over last dim (1024); writes tf32-rounded fp32 directly.
// ---------------------------------------------------------------------------
__global__ __launch_bounds__(256)
void layernorm_round_kernel(const float* __restrict__ x, const float* __restrict__ g,
                            const float* __restrict__ b, float* __restrict__ y)
{
    const long long row = blockIdx.x;
    const int tid = threadIdx.x;
    float4 v = ((const float4*)(x + row * HH))[tid];

    __shared__ float red[8];
    float s = v.x + v.y + v.z + v.w;
    #pragma unroll
    for (int o = 16; o; o >>= 1) s += __shfl_xor_sync(0xffffffffu, s, o);
    if ((tid & 31) == 0) red[tid >> 5] = s;
    __syncthreads();
    float mean = (red[0] + red[1] + red[2] + red[3] +
                  red[4] + red[5] + red[6] + red[7]) * (1.f / HH);
    __syncthreads();

    float dx = v.x - mean, dy = v.y - mean, dz = v.z - mean, dw = v.w - mean;
    float sq = dx * dx + dy * dy + dz * dz + dw * dw;
    #pragma unroll
    for (int o = 16; o; o >>= 1) sq += __shfl_xor_sync(0xffffffffu, sq, o);
    if ((tid & 31) == 0) red[tid >> 5] = sq;
    __syncthreads();
    float var = (red[0] + red[1] + red[2] + red[3] +
                 red[4] + red[5] + red[6] + red[7]) * (1.f / HH);
    float rstd = rsqrtf(var + 1e-5f);

    float4 g4 = ((const float4*)g)[tid];
    float4 b4 = ((const float4*)b)[tid];
    float4 o4;
    o4.x = rna_tf32(dx * rstd * g4.x + b4.x);
    o4.y = rna_tf32(dy * rstd * g4.y + b4.y);
    o4.z = rna_tf32(dz * rstd * g4.z + b4.z);
    o4.w = rna_tf32(dw * rstd * g4.w + b4.w);
    ((float4*)(y + row * HH))[tid] = o4;
}

// ---------------------------------------------------------------------------
// Host orchestration
// ---------------------------------------------------------------------------
extern "C" void kernel_launch(void* const* d_in, const int* in_sizes, int n_in,
                              void* d_out, int out_size)
{
    const float* input_ = (const float*)d_in[0];
    const float* enc    = (const float*)d_in[1];
    const float* Wq_s = (const float*)d_in[4];
    const float* Wk_s = (const float*)d_in[5];
    const float* Wv_s = (const float*)d_in[6];
    const float* Wo_s = (const float*)d_in[7];
    const float* Wq_c = (const float*)d_in[8];
    const float* Wk_c = (const float*)d_in[9];
    const float* Wv_c = (const float*)d_in[10];
    const float* Wo_c = (const float*)d_in[11];
    const float* w1   = (const float*)d_in[12];
    const float* b1   = (const float*)d_in[13];
    const float* w2   = (const float*)d_in[14];
    const float* b2   = (const float*)d_in[15];
    const float* g_mmha = (const float*)d_in[16];
    const float* b_mmha = (const float*)d_in[17];
    const float* g_mha  = (const float*)d_in[18];
    const float* b_mha  = (const float*)d_in[19];
    const float* g_ffn  = (const float*)d_in[20];
    const float* b_ffn  = (const float*)d_in[21];
    float* out = (float*)d_out;

    float *q, *k, *v, *x, *z, *a, *hid, *bw;
    cudaGetSymbolAddress((void**)&q,   ws_q);
    cudaGetSymbolAddress((void**)&k,   ws_k);
    cudaGetSymbolAddress((void**)&v,   ws_v);
    cudaGetSymbolAddress((void**)&x,   ws_x);
    cudaGetSymbolAddress((void**)&z,   ws_z);
    cudaGetSymbolAddress((void**)&a,   ws_a);
    cudaGetSymbolAddress((void**)&hid, ws_hid);
    cudaGetSymbolAddress((void**)&bw,  ws_b);

    cudaFuncSetAttribute(flash_attn_kernel,
                         cudaFuncAttributeMaxDynamicSharedMemorySize, FLASH_SMEM);
    cudaFuncSetAttribute(gemm_tf32_kernel,
                         cudaFuncAttributeMaxDynamicSharedMemorySize, GEMM_SMEM);

    auto roundw = [&](const float* src, float* dst, long long n) {
        round_kernel<<<(int)(n / 1024), 256>>>(src, dst);
    };
    auto gemm = [&](const float* pA, float* C, int M, int N, int K,
                    const float* bias, const float* resid, int relu, int round_out) {
        dim3 grid(N / 128, M / 128, 1);
        gemm_tf32_kernel<<<grid, 256, GEMM_SMEM>>>(pA, bw, C, N, M, N, K,
                                                   bias, resid, N, relu, round_out);
    };
    auto flash = [&](const float* Q, const float* K, const float* V, float* O,
                     int Tk, int causal) {
        dim3 grid(TT / BQ, BB * NHH);
        flash_attn_kernel<<<grid, 256, FLASH_SMEM>>>(Q, K, V, O, Tk, causal);
    };

    const long long nW  = (long long)HH * HH;
    const long long nW1 = (long long)FF * HH;
    const long long nMH = (long long)MM * HH;

    // ---- self attention ----
    layernorm_round_kernel<<<MM, 256>>>(input_, g_mmha, b_mmha, a);
    roundw(Wq_s, bw, nW);  gemm(a, q, MM, HH, HH, nullptr, nullptr, 0, 0);
    roundw(Wk_s, bw, nW);  gemm(a, k, MM, HH, HH, nullptr, nullptr, 0, 0);
    roundw(Wv_s, bw, nW);  gemm(a, v, MM, HH, HH, nullptr, nullptr, 0, 0);
    flash(q, k, v, a, TT, /*causal=*/1);                 // ctx (rounded) -> a
    roundw(Wo_s, bw, nW);  gemm(a, x, MM, HH, HH, nullptr, input_, 0, 0);

    // ---- cross attention ----
    layernorm_round_kernel<<<MM, 256>>>(x, g_mha, b_mha, a);
    roundw(Wq_c, bw, nW);  gemm(a, q, MM, HH, HH, nullptr, nullptr, 0, 0);
    roundw(enc, a, nMH);                                 // enc (rounded) -> a
    roundw(Wk_c, bw, nW);  gemm(a, k, BB * TEE, HH, HH, nullptr, nullptr, 0, 0);
    roundw(Wv_c, bw, nW);  gemm(a, v, BB * TEE, HH, HH, nullptr, nullptr, 0, 0);
    flash(q, k, v, a, TEE, /*causal=*/0);
    roundw(Wo_c, bw, nW);  gemm(a, z, MM, HH, HH, nullptr, x, 0, 0);

    // ---- FFN ----
    layernorm_round_kernel<<<MM, 256>>>(z, g_ffn, b_ffn, a);
    roundw(w1, bw, nW1);   gemm(a, hid, MM, FF, HH, b1, nullptr, 1, 1);
    roundw(w2, bw, nW1);   gemm(hid, out, MM, HH, FF, b2, z, 0, 0);
}

// round 11
// speedup vs baseline: 3.2332x; 1.5146x over previous
#include <cuda_runtime.h>
#include <cuda_bf16.h>
#include <math.h>
#include <stdint.h>

// Problem constants (fixed by the reference setup)
#define BB   8
#define TT   1024
#define TEE  1024
#define HH   1024
#define NHH  8
#define DKK  128
#define MM   (BB * TT)       // 8192 rows
#define FF   4096            // FFN hidden

// ---------------------------------------------------------------------------
// Scratch (static device globals)
// ---------------------------------------------------------------------------
__device__ float ws_q  [MM * HH];
__device__ float ws_k  [MM * HH];
__device__ float ws_v  [MM * HH];
__device__ float ws_x  [MM * HH];
__device__ float ws_z  [MM * HH];
__device__ float ws_a  [MM * HH];    // tf32-rounded A operand (LN out / ctx / enc)
__device__ float ws_hid[MM * FF];    // tf32-rounded FFN hidden
__device__ float ws_b  [FF * HH];    // tf32-rounded weight operand

// ---------------------------------------------------------------------------
// tf32 rna rounding helper
// ---------------------------------------------------------------------------
__device__ __forceinline__ float rna_tf32(float x) {
    uint32_t u;
    asm("cvt.rna.tf32.f32 %0, %1;" : "=r"(u) : "f"(x));
    return __uint_as_float(u);
}

// standalone round: 4 floats/thread; n % 1024 == 0
__global__ __launch_bounds__(256)
void round_kernel(const float* __restrict__ x, float* __restrict__ y)
{
    const long long i = (long long)blockIdx.x * 256 + threadIdx.x;
    float4 v = ((const float4*)x)[i];
    v.x = rna_tf32(v.x); v.y = rna_tf32(v.y);
    v.z = rna_tf32(v.z); v.w = rna_tf32(v.w);
    ((float4*)y)[i] = v;
}

// ---------------------------------------------------------------------------
// MMA / ldmatrix / cp.async primitives
// ---------------------------------------------------------------------------
__device__ __forceinline__ void mma_tf32(float* c, const uint32_t* a, const uint32_t* b) {
    asm volatile(
        "mma.sync.aligned.m16n8k8.row.col.f32.tf32.tf32.f32 "
        "{%0,%1,%2,%3},{%4,%5,%6,%7},{%8,%9},{%0,%1,%2,%3};"
        : "+f"(c[0]), "+f"(c[1]), "+f"(c[2]), "+f"(c[3])
        : "r"(a[0]), "r"(a[1]), "r"(a[2]), "r"(a[3]), "r"(b[0]), "r"(b[1]));
}

__device__ __forceinline__ void ldm_x4(uint32_t addr, uint32_t* r) {
    asm volatile("ldmatrix.sync.aligned.m8n8.x4.shared.b16 {%0,%1,%2,%3}, [%4];"
        : "=r"(r[0]), "=r"(r[1]), "=r"(r[2]), "=r"(r[3]) : "r"(addr));
}

__device__ __forceinline__ void cp_async16(uint32_t smem_addr, const void* gptr) {
    asm volatile("cp.async.cg.shared.global [%0], [%1], 16;"
                 :: "r"(smem_addr), "l"(gptr));
}

// ---------------------------------------------------------------------------
// tf32 tensor-core GEMM (unchanged from R10; validated)
// ---------------------------------------------------------------------------
#define SROWF 36
#define PLANEF (128 * SROWF)
#define BUFF (2 * PLANEF)
#define GEMM_SMEM (2 * BUFF * 4)         // 73728 B

__global__ __launch_bounds__(256, 2)
void gemm_tf32_kernel(const float* __restrict__ A,
                      const float* __restrict__ B,
                      float* __restrict__ C,
                      int ldc, int M, int N, int K,
                      const float* __restrict__ bias,
                      const float* __restrict__ resid, int ldres,
                      int relu, int round_out)
{
    extern __shared__ float smf[];

    const int tid  = threadIdx.x;
    const int warp = tid >> 5;
    const int lane = tid & 31;
    const int wm = warp >> 2;
    const int wn = warp & 3;
    const int qr = lane >> 2;
    const int qc = lane & 3;
    const int m0 = blockIdx.y * 128;
    const int n0 = blockIdx.x * 128;

    const uint32_t sbase = (uint32_t)__cvta_generic_to_shared(smf);

    const int aRow = ((lane >> 3) & 1) * 8 + (lane & 7);
    const int aKof = (lane >> 4) * 4;
    const int bRow = (lane >> 4) * 8 + (lane & 7);
    const int bKof = ((lane >> 3) & 1) * 4;

    float acc[4][4][4];
    #pragma unroll
    for (int mt = 0; mt < 4; ++mt)
        #pragma unroll
        for (int nt = 0; nt < 4; ++nt)
            #pragma unroll
            for (int r = 0; r < 4; ++r) acc[mt][nt][r] = 0.f;

    auto issue = [&](int buf, int kk0) {
        #pragma unroll
        for (int i = 0; i < 8; ++i) {
            const int op   = i >> 2;
            const int widx = (i & 3) * 256 + tid;
            const int row  = widx >> 3;
            const int g    = widx & 7;
            const float* src = op
                ? B + (long long)(n0 + row) * K + kk0 + g * 4
                : A + (long long)(m0 + row) * K + kk0 + g * 4;
            const uint32_t soff = (uint32_t)((buf * BUFF + op * PLANEF + row * SROWF + g * 4) * 4);
            cp_async16(sbase + soff, src);
        }
        asm volatile("cp.async.commit_group;");
    };

    const int nchunks = K >> 5;

    issue(0, 0);
    asm volatile("cp.async.wait_group 0;");
    __syncthreads();

    for (int t = 0; t < nchunks; ++t) {
        const int buf = t & 1;
        if (t + 1 < nchunks) issue(buf ^ 1, (t + 1) * 32);

        const uint32_t bufF = (uint32_t)(buf * BUFF);

        #pragma unroll
        for (int ks = 0; ks < 4; ++ks) {
            const int k0 = ks * 8;
            uint32_t bf[2][4];
            #pragma unroll
            for (int p = 0; p < 2; ++p) {
                const uint32_t off = sbase +
                    (uint32_t)((bufF + PLANEF + (wn * 32 + p * 16 + bRow) * SROWF + k0 + bKof) * 4);
                ldm_x4(off, bf[p]);
            }
            #pragma unroll
            for (int mt = 0; mt < 4; ++mt) {
                uint32_t af[4];
                const uint32_t off = sbase +
                    (uint32_t)((bufF + (wm * 64 + mt * 16 + aRow) * SROWF + k0 + aKof) * 4);
                ldm_x4(off, af);
                #pragma unroll
                for (int nt = 0; nt < 4; ++nt) {
                    const uint32_t* bb = &bf[nt >> 1][(nt & 1) * 2];
                    mma_tf32(acc[mt][nt], af, bb);
                }
            }
        }

        if (t + 1 < nchunks) {
            asm volatile("cp.async.wait_group 0;");
            __syncthreads();
        }
    }

    #pragma unroll
    for (int mt = 0; mt < 4; ++mt) {
        const int row0 = m0 + wm * 64 + mt * 16 + qr;
        #pragma unroll
        for (int nt = 0; nt < 4; ++nt) {
            const int col = n0 + wn * 32 + nt * 8 + qc * 2;
            float2 v0 = make_float2(acc[mt][nt][0], acc[mt][nt][1]);
            float2 v1 = make_float2(acc[mt][nt][2], acc[mt][nt][3]);
            if (bias) {
                float2 b2 = *(const float2*)(bias + col);
                v0.x += b2.x; v0.y += b2.y;
                v1.x += b2.x; v1.y += b2.y;
            }
            if (relu) {
                v0.x = fmaxf(v0.x, 0.f); v0.y = fmaxf(v0.y, 0.f);
                v1.x = fmaxf(v1.x, 0.f); v1.y = fmaxf(v1.y, 0.f);
            }
            if (resid) {
                float2 r0 = *(const float2*)(resid + (long long)row0 * ldres + col);
                float2 r1 = *(const float2*)(resid + (long long)(row0 + 8) * ldres + col);
                v0.x += r0.x; v0.y += r0.y;
                v1.x += r1.x; v1.y += r1.y;
            }
            if (round_out) {
                v0.x = rna_tf32(v0.x); v0.y = rna_tf32(v0.y);
                v1.x = rna_tf32(v1.x); v1.y = rna_tf32(v1.y);
            }
            *(float2*)(C + (long long)row0 * ldc + col)       = v0;
            *(float2*)(C + (long long)(row0 + 8) * ldc + col) = v1;
        }
    }
}

// ---------------------------------------------------------------------------
// Tensor-core flash attention (tf32, DK=128).
// BQ=128 per CTA, 8 warps; warp w owns query rows w*16..w*16+15 across the
// full BK=32 key tile (softmax reductions stay in 4-lane shfl groups).
// Q fragments preloaded to registers; V transposed in smem; P staged via smem
// with rna rounding. Inputs Q/K/V must be pre-rounded to tf32.
// smem: sQ 128x132 (prologue only), then sK 32x132 | sVt 128x36 | sP 128x36.
// ---------------------------------------------------------------------------
#define FBQ 128
#define FBK 32
#define QSTR 132
#define VSTR 36
#define SVT_OFF (FBK * QSTR)             // 4224 floats
#define SP_OFF  (SVT_OFF + 128 * VSTR)   // 8832 floats
#define FLASH_SMEM (FBQ * QSTR * 4)      // 67584 B

__global__ __launch_bounds__(256)
void flash_tc_kernel(const float* __restrict__ Qg, const float* __restrict__ Kg,
                     const float* __restrict__ Vg, float* __restrict__ Og,
                     int Tk, int causal)
{
    extern __shared__ float sm[];
    float* sQ  = sm;
    float* sK  = sm;                 // reuses sQ region after prologue
    float* sVt = sm + SVT_OFF;

    const int tid  = threadIdx.x;
    const int warp = tid >> 5;
    const int lane = tid & 31;
    const int qr = lane >> 2, qc = lane & 3;
    const int q0 = blockIdx.x * FBQ;
    const int bh = blockIdx.y;
    const int bb = bh >> 3, hh = bh & 7;

    const float* Qp = Qg + ((long long)(bb * TT + q0)) * HH + hh * DKK;
    const float* Kp = Kg + ((long long)bb * Tk) * HH + hh * DKK;
    const float* Vp = Vg + ((long long)bb * Tk) * HH + hh * DKK;

    const uint32_t sbase = (uint32_t)__cvta_generic_to_shared(sm);

    const int aRow = ((lane >> 3) & 1) * 8 + (lane & 7);
    const int aKof = (lane >> 4) * 4;
    const int bRow = (lane >> 4) * 8 + (lane & 7);
    const int bKof = ((lane >> 3) & 1) * 4;

    // ---- prologue: Q tile -> smem -> register fragments ----
    #pragma unroll
    for (int i = 0; i < 16; ++i) {
        int idx = i * 256 + tid;               // 4096 float4
        int row = idx >> 5, c4 = (idx & 31) * 4;
        *(float4*)&sQ[row * QSTR + c4] = *(const float4*)(Qp + (long long)row * HH + c4);
    }
    __syncthreads();
    uint32_t qf[16][4];
    {
        const int rb = warp * 16 + aRow;
        #pragma unroll
        for (int ks = 0; ks < 16; ++ks)
            ldm_x4(sbase + (uint32_t)((rb * QSTR + ks * 8 + aKof) * 4), qf[ks]);
    }
    __syncthreads();

    const float scale = 0.08838834764831845f;
    float o[16][4];
    #pragma unroll
    for (int nt = 0; nt < 16; ++nt) {
        o[nt][0] = 0.f; o[nt][1] = 0.f; o[nt][2] = 0.f; o[nt][3] = 0.f;
    }
    float m0 = -INFINITY, m1 = -INFINITY, l0 = 0.f, l1 = 0.f;

    const int nkt = causal ? (q0 / FBK + 4) : (Tk / FBK);

    for (int kt = 0; kt < nkt; ++kt) {
        // K tile (32 x 128) -> sK, coalesced
        #pragma unroll
        for (int i = 0; i < 4; ++i) {
            int idx = i * 256 + tid;
            int row = idx >> 5, c4 = (idx & 31) * 4;
            *(float4*)&sK[row * QSTR + c4] =
                *(const float4*)(Kp + (long long)(kt * FBK + row) * HH + c4);
        }
        // V tile transposed -> sVt[d][k]; lane=k, warp picks d-blocks
        // (conflict-free writes: banks (4d + k) % 32, k spans the warp)
        #pragma unroll
        for (int i = 0; i < 4; ++i) {
            int db = i * 8 + warp;             // 0..31
            float4 v4 = *(const float4*)(Vp + (long long)(kt * FBK + lane) * HH + db * 4);
            sVt[(db * 4 + 0) * VSTR + lane] = v4.x;
            sVt[(db * 4 + 1) * VSTR + lane] = v4.y;
            sVt[(db * 4 + 2) * VSTR + lane] = v4.z;
            sVt[(db * 4 + 3) * VSTR + lane] = v4.w;
        }
        __syncthreads();

        // ---- S = Q K^T ----
        float facc[4][4];
        #pragma unroll
        for (int nt = 0; nt < 4; ++nt) {
            facc[nt][0] = 0.f; facc[nt][1] = 0.f; facc[nt][2] = 0.f; facc[nt][3] = 0.f;
        }
        #pragma unroll
        for (int ks = 0; ks < 16; ++ks) {
            uint32_t bf[2][4];
            #pragma unroll
            for (int p = 0; p < 2; ++p)
                ldm_x4(sbase + (uint32_t)(((p * 16 + bRow) * QSTR + ks * 8 + bKof) * 4), bf[p]);
            #pragma unroll
            for (int nt = 0; nt < 4; ++nt)
                mma_tf32(facc[nt], qf[ks], &bf[nt >> 1][(nt & 1) * 2]);
        }

        // ---- scale + mask + online softmax ----
        const int gq0 = q0 + warp * 16 + qr;
        const int gq1 = gq0 + 8;
        float mx0 = -INFINITY, mx1 = -INFINITY;
        #pragma unroll
        for (int nt = 0; nt < 4; ++nt) {
            const int kc0 = kt * FBK + nt * 8 + 2 * qc;
            facc[nt][0] *= scale; facc[nt][1] *= scale;
            facc[nt][2] *= scale; facc[nt][3] *= scale;
            if (causal) {
                if (kc0     > gq0) facc[nt][0] = -INFINITY;
                if (kc0 + 1 > gq0) facc[nt][1] = -INFINITY;
                if (kc0     > gq1) facc[nt][2] = -INFINITY;
                if (kc0 + 1 > gq1) facc[nt][3] = -INFINITY;
            }
            mx0 = fmaxf(mx0, fmaxf(facc[nt][0], facc[nt][1]));
            mx1 = fmaxf(mx1, fmaxf(facc[nt][2], facc[nt][3]));
        }
        mx0 = fmaxf(mx0, __shfl_xor_sync(0xffffffffu, mx0, 1));
        mx0 = fmaxf(mx0, __shfl_xor_sync(0xffffffffu, mx0, 2));
        mx1 = fmaxf(mx1, __shfl_xor_sync(0xffffffffu, mx1, 1));
        mx1 = fmaxf(mx1, __shfl_xor_sync(0xffffffffu, mx1, 2));
        const float mn0 = fmaxf(m0, mx0), mn1 = fmaxf(m1, mx1);
        const float corr0 = __expf(m0 - mn0), corr1 = __expf(m1 - mn1);

        float rs0 = 0.f, rs1 = 0.f;
        #pragma unroll
        for (int nt = 0; nt < 4; ++nt) {
            float p0 = __expf(facc[nt][0] - mn0), p1 = __expf(facc[nt][1] - mn0);
            float p2 = __expf(facc[nt][2] - mn1), p3 = __expf(facc[nt][3] - mn1);
            rs0 += p0 + p1; rs1 += p2 + p3;
            *(float2*)&sm[SP_OFF + (warp * 16 + qr) * VSTR + nt * 8 + 2 * qc] =
                make_float2(rna_tf32(p0), rna_tf32(p1));
            *(float2*)&sm[SP_OFF + (warp * 16 + qr + 8) * VSTR + nt * 8 + 2 * qc] =
                make_float2(rna_tf32(p2), rna_tf32(p3));
        }
        rs0 += __shfl_xor_sync(0xffffffffu, rs0, 1);
        rs0 += __shfl_xor_sync(0xffffffffu, rs0, 2);
        rs1 += __shfl_xor_sync(0xffffffffu, rs1, 1);
        rs1 += __shfl_xor_sync(0xffffffffu, rs1, 2);
        l0 = l0 * corr0 + rs0;  l1 = l1 * corr1 + rs1;
        m0 = mn0;  m1 = mn1;
        #pragma unroll
        for (int nt = 0; nt < 16; ++nt) {
            o[nt][0] *= corr0; o[nt][1] *= corr0;
            o[nt][2] *= corr1; o[nt][3] *= corr1;
        }
        __syncwarp();   // P region is warp-private; warp-level visibility enough

        // ---- O += P V ----
        #pragma unroll
        for (int ks = 0; ks < 4; ++ks) {
            uint32_t af[4];
            ldm_x4(sbase + (uint32_t)((SP_OFF + (warp * 16 + aRow) * VSTR + ks * 8 + aKof) * 4), af);
            #pragma unroll
            for (int p = 0; p < 8; ++p) {
                uint32_t bf[4];
                ldm_x4(sbase + (uint32_t)((SVT_OFF + (p * 16 + bRow) * VSTR + ks * 8 + bKof) * 4), bf);
                mma_tf32(o[p * 2],     af, &bf[0]);
                mma_tf32(o[p * 2 + 1], af, &bf[2]);
            }
        }
        __syncthreads();   // all warps done with sK/sVt before next overwrite
    }

    // ---- finalize + store (rna-rounded: ctx feeds the Wo/Wo_c GEMM) ----
    const float inv0 = 1.f / l0, inv1 = 1.f / l1;
    const long long r0 = ((long long)(bb * TT + q0 + warp * 16 + qr)) * HH + hh * DKK;
    const long long r1 = r0 + 8LL * HH;
    #pragma unroll
    for (int nt = 0; nt < 16; ++nt) {
        const int d = nt * 8 + 2 * qc;
        *(float2*)(Og + r0 + d) =
            make_float2(rna_tf32(o[nt][0] * inv0), rna_tf32(o[nt][1] * inv0));
        *(float2*)(Og + r1 + d) =
            make_float2(rna_tf32(o[nt][2] * inv1), rna_tf32(o[nt][3] * inv1));
    }
}

// ---------------------------------------------------------------------------
// LayerNorm over last dim (1024); writes tf32-rounded fp32 directly.
// ---------------------------------------------------------------------------
__global__ __launch_bounds__(256)
void layernorm_round_kernel(const float* __restrict__ x, const float* __restrict__ g,
                            const float* __restrict__ b, float* __restrict__ y)
{
    const long long row = blockIdx.x;
    const int tid = threadIdx.x;
    float4 v = ((const float4*)(x + row * HH))[tid];

    __shared__ float red[8];
    float s = v.x + v.y + v.z + v.w;
    #pragma unroll
    for (int o = 16; o; o >>= 1) s += __shfl_xor_sync(0xffffffffu, s, o);
    if ((tid & 31) == 0) red[tid >> 5] = s;
    __syncthreads();
    float mean = (red[0] + red[1] + red[2] + red[3] +
                  red[4] + red[5] + red[6] + red[7]) * (1.f / HH);
    __syncthreads();

    float dx = v.x - mean, dy = v.y - mean, dz = v.z - mean, dw = v.w - mean;
    float sq = dx * dx + dy * dy + dz * dz + dw * dw;
    #pragma unroll
    for (int o = 16; o; o >>= 1) sq += __shfl_xor_sync(0xffffffffu, sq, o);
    if ((tid & 31) == 0) red[tid >> 5] = sq;
    __syncthreads();
    float var = (red[0] + red[1] + red[2] + red[3] +
                 red[4] + red[5] + red[6] + red[7]) * (1.f / HH);
    float rstd = rsqrtf(var + 1e-5f);

    float4 g4 = ((const float4*)g)[tid];
    float4 b4 = ((const float4*)b)[tid];
    float4 o4;
    o4.x = rna_tf32(dx * rstd * g4.x + b4.x);
    o4.y = rna_tf32(dy * rstd * g4.y + b4.y);
    o4.z = rna_tf32(dz * rstd * g4.z + b4.z);
    o4.w = rna_tf32(dw * rstd * g4.w + b4.w);
    ((float4*)(y + row * HH))[tid] = o4;
}

// ---------------------------------------------------------------------------
// Host orchestration
// ---------------------------------------------------------------------------
extern "C" void kernel_launch(void* const* d_in, const int* in_sizes, int n_in,
                              void* d_out, int out_size)
{
    const float* input_ = (const float*)d_in[0];
    const float* enc    = (const float*)d_in[1];
    const float* Wq_s = (const float*)d_in[4];
    const float* Wk_s = (const float*)d_in[5];
    const float* Wv_s = (const float*)d_in[6];
    const float* Wo_s = (const float*)d_in[7];
    const float* Wq_c = (const float*)d_in[8];
    const float* Wk_c = (const float*)d_in[9];
    const float* Wv_c = (const float*)d_in[10];
    const float* Wo_c = (const float*)d_in[11];
    const float* w1   = (const float*)d_in[12];
    const float* b1   = (const float*)d_in[13];
    const float* w2   = (const float*)d_in[14];
    const float* b2   = (const float*)d_in[15];
    const float* g_mmha = (const float*)d_in[16];
    const float* b_mmha = (const float*)d_in[17];
    const float* g_mha  = (const float*)d_in[18];
    const float* b_mha  = (const float*)d_in[19];
    const float* g_ffn  = (const float*)d_in[20];
    const float* b_ffn  = (const float*)d_in[21];
    float* out = (float*)d_out;

    float *q, *k, *v, *x, *z, *a, *hid, *bw;
    cudaGetSymbolAddress((void**)&q,   ws_q);
    cudaGetSymbolAddress((void**)&k,   ws_k);
    cudaGetSymbolAddress((void**)&v,   ws_v);
    cudaGetSymbolAddress((void**)&x,   ws_x);
    cudaGetSymbolAddress((void**)&z,   ws_z);
    cudaGetSymbolAddress((void**)&a,   ws_a);
    cudaGetSymbolAddress((void**)&hid, ws_hid);
    cudaGetSymbolAddress((void**)&bw,  ws_b);

    cudaFuncSetAttribute(flash_tc_kernel,
                         cudaFuncAttributeMaxDynamicSharedMemorySize, FLASH_SMEM);
    cudaFuncSetAttribute(gemm_tf32_kernel,
                         cudaFuncAttributeMaxDynamicSharedMemorySize, GEMM_SMEM);

    auto roundw = [&](const float* src, float* dst, long long n) {
        round_kernel<<<(int)(n / 1024), 256>>>(src, dst);
    };
    auto gemm = [&](const float* pA, float* C, int M, int N, int K,
                    const float* bias, const float* resid, int relu, int round_out) {
        dim3 grid(N / 128, M / 128, 1);
        gemm_tf32_kernel<<<grid, 256, GEMM_SMEM>>>(pA, bw, C, N, M, N, K,
                                                   bias, resid, N, relu, round_out);
    };
    auto flash = [&](const float* Q, const float* K, const float* V, float* O,
                     int Tk, int causal) {
        dim3 grid(TT / FBQ, BB * NHH);
        flash_tc_kernel<<<grid, 256, FLASH_SMEM>>>(Q, K, V, O, Tk, causal);
    };

    const long long nW  = (long long)HH * HH;
    const long long nW1 = (long long)FF * HH;
    const long long nMH = (long long)MM * HH;

    // ---- self attention ----  (q,k,v rounded in epilogue: feed tf32 flash)
    layernorm_round_kernel<<<MM, 256>>>(input_, g_mmha, b_mmha, a);
    roundw(Wq_s, bw, nW);  gemm(a, q, MM, HH, HH, nullptr, nullptr, 0, 1);
    roundw(Wk_s, bw, nW);  gemm(a, k, MM, HH, HH, nullptr, nullptr, 0, 1);
    roundw(Wv_s, bw, nW);  gemm(a, v, MM, HH, HH, nullptr, nullptr, 0, 1);
    flash(q, k, v, a, TT, /*causal=*/1);                 // ctx (rounded) -> a
    roundw(Wo_s, bw, nW);  gemm(a, x, MM, HH, HH, nullptr, input_, 0, 0);

    // ---- cross attention ----
    layernorm_round_kernel<<<MM, 256>>>(x, g_mha, b_mha, a);
    roundw(Wq_c, bw, nW);  gemm(a, q, MM, HH, HH, nullptr, nullptr, 0, 1);
    roundw(enc, a, nMH);                                 // enc (rounded) -> a
    roundw(Wk_c, bw, nW);  gemm(a, k, BB * TEE, HH, HH, nullptr, nullptr, 0, 1);
    roundw(Wv_c, bw, nW);  gemm(a, v, BB * TEE, HH, HH, nullptr, nullptr, 0, 1);
    flash(q, k, v, a, TEE, /*causal=*/0);
    roundw(Wo_c, bw, nW);  gemm(a, z, MM, HH, HH, nullptr, x, 0, 0);

    // ---- FFN ----
    layernorm_round_kernel<<<MM, 256>>>(z, g_ffn, b_ffn, a);
    roundw(w1, bw, nW1);   gemm(a, hid, MM, FF, HH, b1, nullptr, 1, 1);
    roundw(w2, bw, nW1);   gemm(hid, out, MM, HH, FF, b2, z, 0, 0);
}